// round 11
// baseline (speedup 1.0000x reference)
#include <cuda_runtime.h>
#include <stdint.h>
#include <math.h>

#define POINCARE_BOUND 0.99999f
typedef unsigned long long u64;

// ---------------------------------------------------------------------------
// Weights live in BOTH constant memory and global memory (same layout).
// Each matvec splits column chunks: half loaded via LDC (8-cyc port floor),
// half via uniform LDG.128 (4-cyc LSU floor, L1-resident), interleaved
// within each k-iteration so both ports run concurrently.
// ---------------------------------------------------------------------------
__constant__ __align__(16) float cWc1[32 * 64];
__constant__ __align__(16) float cWc2[32 * 64];
__constant__ __align__(16) float cW0 [64 * 64];
__constant__ __align__(16) float cW1 [64 * 32];
__constant__ __align__(16) float cbc [64];
__constant__ __align__(16) float cb0 [64];
__constant__ __align__(16) float cb1 [32];

// ---------------------------------------------------------------------------
// packed f32x2 primitives
// ---------------------------------------------------------------------------
__device__ __forceinline__ u64 pk2(float lo, float hi) {
    u64 r; asm("mov.b64 %0, {%1, %2};" : "=l"(r) : "f"(lo), "f"(hi)); return r;
}
__device__ __forceinline__ void upk2(u64 v, float& lo, float& hi) {
    asm("mov.b64 {%0, %1}, %2;" : "=f"(lo), "=f"(hi) : "l"(v));
}
__device__ __forceinline__ u64 fma2(u64 a, u64 b, u64 c) {
    u64 d; asm("fma.rn.f32x2 %0, %1, %2, %3;" : "=l"(d) : "l"(a), "l"(b), "l"(c)); return d;
}
__device__ __forceinline__ u64 mul2(u64 a, u64 b) {
    u64 d; asm("mul.rn.f32x2 %0, %1, %2;" : "=l"(d) : "l"(a), "l"(b)); return d;
}
__device__ __forceinline__ float hsum2(u64 v) {
    float lo, hi; upk2(v, lo, hi); return lo + hi;
}

// ---------------------------------------------------------------------------
// fast scalar math (MUFU approx; operand norms are O(1) here)
// ---------------------------------------------------------------------------
__device__ __forceinline__ float rcpf(float x)  { float r; asm("rcp.approx.f32 %0, %1;"  : "=f"(r) : "f"(x)); return r; }
__device__ __forceinline__ float sqrtfa(float x){ float r; asm("sqrt.approx.f32 %0, %1;" : "=f"(r) : "f"(x)); return r; }
__device__ __forceinline__ float lg2fa(float x) { float r; asm("lg2.approx.f32 %0, %1;"  : "=f"(r) : "f"(x)); return r; }
__device__ __forceinline__ float ex2fa(float x) { float r; asm("ex2.approx.f32 %0, %1;"  : "=f"(r) : "f"(x)); return r; }

__device__ __forceinline__ float log_scale(float ss) {    // atanh(min(n,B))/n
    float n = fmaxf(sqrtfa(ss), 1e-15f);
    float m = fminf(n, POINCARE_BOUND);
    float r = (1.f + m) * rcpf(1.f - m);
    return (0.34657359f * lg2fa(r)) * rcpf(n);
}
__device__ __forceinline__ float exp_scale(float ss) {     // tanh(n)/n
    float n = fmaxf(sqrtfa(ss), 1e-15f);
    float e = ex2fa(n * -2.8853901f);
    return ((1.f - e) * rcpf(1.f + e)) * rcpf(n);
}

// ---------------------------------------------------------------------------
// packed vector ops
// ---------------------------------------------------------------------------
template<int D2>
__device__ __forceinline__ float ssum2(const u64* v) {
    u64 a = 0ull;
#pragma unroll
    for (int i = 0; i < D2; ++i) a = fma2(v[i], v[i], a);
    return hsum2(a);
}
template<int D2>
__device__ __forceinline__ void scale2(u64* v, float s) {
    const u64 s2 = pk2(s, s);
#pragma unroll
    for (int i = 0; i < D2; ++i) v[i] = mul2(v[i], s2);
}
template<int D2>
__device__ __forceinline__ void logmap0p(u64* v) { scale2<D2>(v, log_scale(ssum2<D2>(v))); }
template<int D2>
__device__ __forceinline__ void expmap0p(u64* v) { scale2<D2>(v, exp_scale(ssum2<D2>(v))); }

template<int D2>
__device__ __forceinline__ void mobius_addp(u64* x, const u64* y) {
    u64 ax = 0ull, ay = 0ull, axy = 0ull;
#pragma unroll
    for (int i = 0; i < D2; ++i) {
        u64 yi = y[i];
        ax  = fma2(x[i], x[i], ax);
        ay  = fma2(yi,  yi,  ay);
        axy = fma2(x[i], yi, axy);
    }
    float x2 = hsum2(ax), y2 = hsum2(ay), xy = hsum2(axy);
    float a   = 1.f + 2.f * xy + y2;
    float b   = 1.f - x2;
    float inv = rcpf(fmaxf(1.f + 2.f * xy + x2 * y2, 1e-15f));
    const u64 a2 = pk2(a * inv, a * inv);
    const u64 b2 = pk2(b * inv, b * inv);
#pragma unroll
    for (int i = 0; i < D2; ++i)
        x[i] = fma2(b2, y[i], mul2(a2, x[i]));
}

// dual-source matvec: o2[OUT/2] = v2[IN/2] @ W[IN][OUT].
// Output processed in 32-column passes; within each k2 iteration the first
// 16 columns load from __constant__ (LDC.128) and the next 16 from global
// via __ldg (LDG.128, L1-resident) — both ports active in the same window.
template<int IN, int OUT>
__device__ __forceinline__ void mvDual(const u64* v2, const float* cW,
                                       const float* __restrict__ gW, u64* o2) {
#pragma unroll
    for (int c0 = 0; c0 < OUT; c0 += 32) {
        u64 acc[16];
#pragma unroll
        for (int j = 0; j < 16; ++j) acc[j] = 0ull;
#pragma unroll
        for (int k2 = 0; k2 < IN / 2; ++k2) {
            float lo, hi; upk2(v2[k2], lo, hi);
            const u64 va = pk2(lo, lo), vb = pk2(hi, hi);
            const ulonglong2* c0p = reinterpret_cast<const ulonglong2*>(cW + (2 * k2)     * OUT + c0);
            const ulonglong2* c1p = reinterpret_cast<const ulonglong2*>(cW + (2 * k2 + 1) * OUT + c0);
            const ulonglong2* g0p = reinterpret_cast<const ulonglong2*>(gW + (2 * k2)     * OUT + c0 + 16);
            const ulonglong2* g1p = reinterpret_cast<const ulonglong2*>(gW + (2 * k2 + 1) * OUT + c0 + 16);
#pragma unroll
            for (int j = 0; j < 4; ++j) {
                ulonglong2 wc = c0p[j];                 // LDC cols [c0, c0+16)
                acc[2 * j]     = fma2(va, wc.x, acc[2 * j]);
                acc[2 * j + 1] = fma2(va, wc.y, acc[2 * j + 1]);
                ulonglong2 wg = __ldg(g0p + j);          // LDG cols [c0+16, c0+32)
                acc[8 + 2 * j]     = fma2(va, wg.x, acc[8 + 2 * j]);
                acc[8 + 2 * j + 1] = fma2(va, wg.y, acc[8 + 2 * j + 1]);
                ulonglong2 xc = c1p[j];
                acc[2 * j]     = fma2(vb, xc.x, acc[2 * j]);
                acc[2 * j + 1] = fma2(vb, xc.y, acc[2 * j + 1]);
                ulonglong2 xg = __ldg(g1p + j);
                acc[8 + 2 * j]     = fma2(vb, xg.x, acc[8 + 2 * j]);
                acc[8 + 2 * j + 1] = fma2(vb, xg.y, acc[8 + 2 * j + 1]);
            }
        }
#pragma unroll
        for (int j = 0; j < 16; ++j) o2[c0 / 2 + j] = acc[j];
    }
}

// load one 32-wide row, pack, apply logmap0
__device__ __forceinline__ void load_log32p(const float* __restrict__ gx, int row, u64* v2) {
    const float4* xp = reinterpret_cast<const float4*>(gx + (size_t)row * 32);
    u64 a = 0ull;
#pragma unroll
    for (int i = 0; i < 8; ++i) {
        float4 v = xp[i];
        u64 p0 = pk2(v.x, v.y), p1 = pk2(v.z, v.w);
        v2[2 * i] = p0; v2[2 * i + 1] = p1;
        a = fma2(p0, p0, a);
        a = fma2(p1, p1, a);
    }
    scale2<16>(v2, log_scale(hsum2(a)));
}

// ---------------------------------------------------------------------------
// kernel: one thread per row; each matvec split LDC/LDG per column half
// ---------------------------------------------------------------------------
__global__ void __launch_bounds__(128, 4)
poincare_mlp_kernel(const float* __restrict__ gx1,
                    const float* __restrict__ gx2,
                    const float* __restrict__ gWc1,
                    const float* __restrict__ gWc2,
                    const float* __restrict__ gW0,
                    const float* __restrict__ gW1,
                    float* __restrict__ gout,
                    int N)
{
    const int row = blockIdx.x * 128 + threadIdx.x;
    if (row >= N) return;

    u64 u2[16];
    u64 h1[32], h2[32];

    // ---- branch 1: h1 = expmap0(logmap0(x1) @ Wc1)
    load_log32p(gx1, row, u2);
    mvDual<32, 64>(u2, cWc1, gWc1, h1);
    expmap0p<32>(h1);

    // ---- branch 2: h2 = expmap0(logmap0(x2) @ Wc2)
    load_log32p(gx2, row, u2);
    mvDual<32, 64>(u2, cWc2, gWc2, h2);
    expmap0p<32>(h2);

    // ---- h = mobius_add(mobius_add(h1, h2), bc)
    mobius_addp<32>(h1, h2);
    mobius_addp<32>(h1, reinterpret_cast<const u64*>(cbc));

    // ---- layer 0: mobius_add(expmap0(logmap0(h) @ W0), b0)
    logmap0p<32>(h1);
    mvDual<64, 64>(h1, cW0, gW0, h2);
    expmap0p<32>(h2);
    mobius_addp<32>(h2, reinterpret_cast<const u64*>(cb0));

    // ---- layer 1: mobius_add(expmap0(logmap0(h) @ W1), b1)
    logmap0p<32>(h2);
    u64 o2[16];
    mvDual<64, 32>(h2, cW1, gW1, o2);
    expmap0p<16>(o2);
    mobius_addp<16>(o2, reinterpret_cast<const u64*>(cb1));

    float4* op = reinterpret_cast<float4*>(gout + (size_t)row * 32);
#pragma unroll
    for (int i = 0; i < 8; ++i) {
        float x, y, z, w;
        upk2(o2[2 * i],     x, y);
        upk2(o2[2 * i + 1], z, w);
        op[i] = make_float4(x, y, z, w);
    }
}

// ---------------------------------------------------------------------------
// launch
// ---------------------------------------------------------------------------
extern "C" void kernel_launch(void* const* d_in, const int* in_sizes, int n_in,
                              void* d_out, int out_size)
{
    const float* x1  = (const float*)d_in[0];
    const float* x2  = (const float*)d_in[1];
    const float* Wc1 = (const float*)d_in[2];
    const float* Wc2 = (const float*)d_in[3];
    const float* W0  = (const float*)d_in[5];
    const float* W1  = (const float*)d_in[7];

    cudaMemcpyToSymbolAsync(cWc1, d_in[2], 32 * 64 * sizeof(float), 0, cudaMemcpyDeviceToDevice);
    cudaMemcpyToSymbolAsync(cWc2, d_in[3], 32 * 64 * sizeof(float), 0, cudaMemcpyDeviceToDevice);
    cudaMemcpyToSymbolAsync(cbc,  d_in[4], 64 * sizeof(float),      0, cudaMemcpyDeviceToDevice);
    cudaMemcpyToSymbolAsync(cW0,  d_in[5], 64 * 64 * sizeof(float), 0, cudaMemcpyDeviceToDevice);
    cudaMemcpyToSymbolAsync(cb0,  d_in[6], 64 * sizeof(float),      0, cudaMemcpyDeviceToDevice);
    cudaMemcpyToSymbolAsync(cW1,  d_in[7], 64 * 32 * sizeof(float), 0, cudaMemcpyDeviceToDevice);
    cudaMemcpyToSymbolAsync(cb1,  d_in[8], 32 * sizeof(float),      0, cudaMemcpyDeviceToDevice);

    float* out = (float*)d_out;
    const int N = in_sizes[0] / 32;
    const int blocks = (N + 127) / 128;
    poincare_mlp_kernel<<<blocks, 128>>>(x1, x2, Wc1, Wc2, W0, W1, out, N);
}

// round 12
// speedup vs baseline: 1.7522x; 1.7522x over previous
#include <cuda_runtime.h>
#include <stdint.h>
#include <math.h>

#define POINCARE_BOUND 0.99999f
typedef unsigned long long u64;

// ---------------------------------------------------------------------------
// weights + biases in constant memory (LDC.128, warp-uniform immediate addr)
// ---------------------------------------------------------------------------
__constant__ __align__(16) float cWc1[32 * 64];
__constant__ __align__(16) float cWc2[32 * 64];
__constant__ __align__(16) float cW0 [64 * 64];
__constant__ __align__(16) float cW1 [64 * 32];
__constant__ __align__(16) float cbc [64];
__constant__ __align__(16) float cb0 [64];
__constant__ __align__(16) float cb1 [32];

// ---------------------------------------------------------------------------
// packed f32x2 primitives
// ---------------------------------------------------------------------------
__device__ __forceinline__ u64 pk2(float lo, float hi) {
    u64 r; asm("mov.b64 %0, {%1, %2};" : "=l"(r) : "f"(lo), "f"(hi)); return r;
}
__device__ __forceinline__ void upk2(u64 v, float& lo, float& hi) {
    asm("mov.b64 {%0, %1}, %2;" : "=f"(lo), "=f"(hi) : "l"(v));
}
__device__ __forceinline__ u64 fma2(u64 a, u64 b, u64 c) {
    u64 d; asm("fma.rn.f32x2 %0, %1, %2, %3;" : "=l"(d) : "l"(a), "l"(b), "l"(c)); return d;
}
__device__ __forceinline__ u64 mul2(u64 a, u64 b) {
    u64 d; asm("mul.rn.f32x2 %0, %1, %2;" : "=l"(d) : "l"(a), "l"(b)); return d;
}
__device__ __forceinline__ float hsum2(u64 v) {
    float lo, hi; upk2(v, lo, hi); return lo + hi;
}

// ---------------------------------------------------------------------------
// fast scalar math
// ---------------------------------------------------------------------------
__device__ __forceinline__ float rcpf(float x)  { float r; asm("rcp.approx.f32 %0, %1;"  : "=f"(r) : "f"(x)); return r; }
__device__ __forceinline__ float sqrtfa(float x){ float r; asm("sqrt.approx.f32 %0, %1;" : "=f"(r) : "f"(x)); return r; }
__device__ __forceinline__ float lg2fa(float x) { float r; asm("lg2.approx.f32 %0, %1;"  : "=f"(r) : "f"(x)); return r; }
__device__ __forceinline__ float ex2fa(float x) { float r; asm("ex2.approx.f32 %0, %1;"  : "=f"(r) : "f"(x)); return r; }

__device__ __forceinline__ float log_scale(float ss) {    // atanh(min(n,B))/n
    float n = fmaxf(sqrtfa(ss), 1e-15f);
    float m = fminf(n, POINCARE_BOUND);
    float r = (1.f + m) * rcpf(1.f - m);
    return (0.34657359f * lg2fa(r)) * rcpf(n);
}
__device__ __forceinline__ float exp_scale(float ss) {     // tanh(n)/n
    float n = fmaxf(sqrtfa(ss), 1e-15f);
    float e = ex2fa(n * -2.8853901f);
    return ((1.f - e) * rcpf(1.f + e)) * rcpf(n);
}
__device__ __forceinline__ void mobius_coef(float x2, float y2, float xy, float& a, float& b) {
    float inv = rcpf(fmaxf(1.f + 2.f * xy + x2 * y2, 1e-15f));
    a = (1.f + 2.f * xy + y2) * inv;
    b = (1.f - x2) * inv;
}
// concat chain: v = fa*raw1 + fb*raw2 + fc*bc   (round-7 validated math)
__device__ __forceinline__ void concat_coefs(float ss1, float ss2, float d12,
                                             float d1c, float d2c, float bc2,
                                             float& fa, float& fb, float& fc) {
    float s1 = exp_scale(ss1), s2 = exp_scale(ss2);
    float a, b; mobius_coef(s1*s1*ss1, s2*s2*ss2, s1*s2*d12, a, b);
    float p = a * s1, q = b * s2;
    float m2  = p*p*ss1 + q*q*ss2 + 2.f*p*q*d12;
    float mbc = p*d1c + q*d2c;
    float a2, b2; mobius_coef(m2, bc2, mbc, a2, b2);
    float al = a2 * p, be = a2 * q, gc = b2;
    float g2 = al*al*ss1 + be*be*ss2 + gc*gc*bc2
             + 2.f*(al*be*d12 + al*gc*d1c + be*gc*d2c);
    float sL = log_scale(g2);
    fa = sL * al; fb = sL * be; fc = sL * gc;
}
__device__ __forceinline__ void layer_coefs(float ss, float d, float bsq,
                                            float& fg, float& fd) {
    float s = exp_scale(ss);
    float a, b; mobius_coef(s*s*ss, bsq, s*d, a, b);
    float ga = a * s, de = b;
    float g2 = ga*ga*ss + de*de*bsq + 2.f*ga*de*d;
    float sL = log_scale(g2);
    fg = sL * ga; fd = sL * de;
}
__device__ __forceinline__ void out_coefs(float ss, float d, float bsq,
                                          float& pa, float& pb) {
    float s = exp_scale(ss);
    float a, b; mobius_coef(s*s*ss, bsq, s*d, a, b);
    pa = a * s; pb = b;
}

// ---------------------------------------------------------------------------
// matvec stage: dst[col][row] = sum_k src[k][row] * W[k][col]
// smem column-major u64 slots: buf[slot*128 + row], slot j2 packs cols/k 2j2,2j2+1.
// warp w handles cols [Cw, Cw+C); each thread rows 4*lane..4*lane+3.
// ---------------------------------------------------------------------------
template<int K, int OUT>
__device__ __forceinline__ void matvec_stage(const u64* __restrict__ src,
                                             const float* cW,
                                             u64* __restrict__ dst,
                                             int w, int lane) {
    constexpr int C = OUT / 4;
    const int cbase = C * w;
    const int r0 = lane * 4;
    u64 acc[4][C / 2];
#pragma unroll
    for (int j = 0; j < 4; ++j)
#pragma unroll
        for (int c = 0; c < C / 2; ++c) acc[j][c] = 0ull;

#pragma unroll
    for (int k2 = 0; k2 < K / 2; ++k2) {
        const ulonglong2* sp = reinterpret_cast<const ulonglong2*>(src + k2 * 128 + r0);
        ulonglong2 vp0 = sp[0];     // rows r0, r0+1 : (v[2k2], v[2k2+1]) each
        ulonglong2 vp1 = sp[1];     // rows r0+2, r0+3
        float l0,h0,l1,h1,l2,h2,l3,h3;
        upk2(vp0.x,l0,h0); upk2(vp0.y,l1,h1);
        upk2(vp1.x,l2,h2); upk2(vp1.y,l3,h3);
        u64 m0a = pk2(l0,l0), m0b = pk2(h0,h0);
        u64 m1a = pk2(l1,l1), m1b = pk2(h1,h1);
        u64 m2a = pk2(l2,l2), m2b = pk2(h2,h2);
        u64 m3a = pk2(l3,l3), m3b = pk2(h3,h3);
        const ulonglong2* w0 = reinterpret_cast<const ulonglong2*>(cW + (2*k2)   * OUT + cbase);
        const ulonglong2* w1 = reinterpret_cast<const ulonglong2*>(cW + (2*k2+1) * OUT + cbase);
#pragma unroll
        for (int q = 0; q < C / 4; ++q) {
            ulonglong2 wa = w0[q];      // k=2k2, cols 4q..4q+3
            ulonglong2 wb = w1[q];      // k=2k2+1
            acc[0][2*q]   = fma2(m0a, wa.x, acc[0][2*q]);
            acc[0][2*q+1] = fma2(m0a, wa.y, acc[0][2*q+1]);
            acc[0][2*q]   = fma2(m0b, wb.x, acc[0][2*q]);
            acc[0][2*q+1] = fma2(m0b, wb.y, acc[0][2*q+1]);
            acc[1][2*q]   = fma2(m1a, wa.x, acc[1][2*q]);
            acc[1][2*q+1] = fma2(m1a, wa.y, acc[1][2*q+1]);
            acc[1][2*q]   = fma2(m1b, wb.x, acc[1][2*q]);
            acc[1][2*q+1] = fma2(m1b, wb.y, acc[1][2*q+1]);
            acc[2][2*q]   = fma2(m2a, wa.x, acc[2][2*q]);
            acc[2][2*q+1] = fma2(m2a, wa.y, acc[2][2*q+1]);
            acc[2][2*q]   = fma2(m2b, wb.x, acc[2][2*q]);
            acc[2][2*q+1] = fma2(m2b, wb.y, acc[2][2*q+1]);
            acc[3][2*q]   = fma2(m3a, wa.x, acc[3][2*q]);
            acc[3][2*q+1] = fma2(m3a, wa.y, acc[3][2*q+1]);
            acc[3][2*q]   = fma2(m3b, wb.x, acc[3][2*q]);
            acc[3][2*q+1] = fma2(m3b, wb.y, acc[3][2*q+1]);
        }
    }
#pragma unroll
    for (int c2 = 0; c2 < C / 2; ++c2) {
        ulonglong2* dp = reinterpret_cast<ulonglong2*>(dst + (cbase/2 + c2) * 128 + r0);
        dp[0] = make_ulonglong2(acc[0][c2], acc[1][c2]);
        dp[1] = make_ulonglong2(acc[2][c2], acc[3][c2]);
    }
}

// ---------------------------------------------------------------------------
// kernel: CTA = 128 rows; intermediates in smem; per-stage work repartition
// ---------------------------------------------------------------------------
__global__ void __launch_bounds__(128, 2)
poincare_mlp_kernel(const float* __restrict__ gx1,
                    const float* __restrict__ gx2,
                    float* __restrict__ gout,
                    int N)
{
    extern __shared__ __align__(16) u64 sm[];
    u64* A  = sm;               // 32*128 slots (raw1 -> v -> raw4)
    u64* B  = sm + 32 * 128;    // 32*128 slots (raw2 -> raw3)
    u64* U  = sm + 64 * 128;    // 16*128 slots (logmap'd input staging, unscaled)
    float* sS1 = reinterpret_cast<float*>(sm + 80 * 128);
    float* sS2 = sS1 + 128;

    const int tid  = threadIdx.x;
    const int w    = tid >> 5;
    const int lane = tid & 31;
    int row = blockIdx.x * 128 + tid;
    row = row < N ? row : N - 1;

    // per-thread bias self-dots (warp-uniform LDC, cheap)
    float bc2, b0sq, b1sq;
    {
        const u64* b = reinterpret_cast<const u64*>(cbc);
        u64 a = 0ull;
#pragma unroll
        for (int i = 0; i < 32; ++i) a = fma2(b[i], b[i], a);
        bc2 = hsum2(a);
        b = reinterpret_cast<const u64*>(cb0); a = 0ull;
#pragma unroll
        for (int i = 0; i < 32; ++i) a = fma2(b[i], b[i], a);
        b0sq = hsum2(a);
        b = reinterpret_cast<const u64*>(cb1); a = 0ull;
#pragma unroll
        for (int i = 0; i < 16; ++i) a = fma2(b[i], b[i], a);
        b1sq = hsum2(a);
    }

    // ---- S0a: x1 row -> U (unscaled), stash |x1|^2 ----
    {
        const float4* xp = reinterpret_cast<const float4*>(gx1 + (size_t)row * 32);
        u64 a = 0ull;
#pragma unroll
        for (int i = 0; i < 8; ++i) {
            float4 v = xp[i];
            u64 p0 = pk2(v.x, v.y), p1 = pk2(v.z, v.w);
            a = fma2(p0, p0, a); a = fma2(p1, p1, a);
            U[(2*i) * 128 + tid] = p0;
            U[(2*i+1) * 128 + tid] = p1;
        }
        sS1[tid] = hsum2(a);
    }
    __syncthreads();

    // ---- S1: A = U @ Wc1 (raw; logmap scale folded into scalar chain) ----
    matvec_stage<32, 64>(U, cWc1, A, w, lane);
    __syncthreads();

    // ---- S0b: x2 row -> U, stash |x2|^2 ----
    {
        const float4* xp = reinterpret_cast<const float4*>(gx2 + (size_t)row * 32);
        u64 a = 0ull;
#pragma unroll
        for (int i = 0; i < 8; ++i) {
            float4 v = xp[i];
            u64 p0 = pk2(v.x, v.y), p1 = pk2(v.z, v.w);
            a = fma2(p0, p0, a); a = fma2(p1, p1, a);
            U[(2*i) * 128 + tid] = p0;
            U[(2*i+1) * 128 + tid] = p1;
        }
        sS2[tid] = hsum2(a);
    }
    __syncthreads();

    // ---- S2: B = U @ Wc2 ----
    matvec_stage<32, 64>(U, cWc2, B, w, lane);
    __syncthreads();

    // ---- S3: concat chain (per row); A <- fa*A + fb*B + fc*bc ----
    {
        const u64* bcp = reinterpret_cast<const u64*>(cbc);
        u64 aa = 0, bb = 0, ab = 0, ac = 0, bcd = 0;
#pragma unroll
        for (int j = 0; j < 32; ++j) {
            u64 av = A[j * 128 + tid], bv = B[j * 128 + tid], cv = bcp[j];
            aa  = fma2(av, av, aa);
            bb  = fma2(bv, bv, bb);
            ab  = fma2(av, bv, ab);
            ac  = fma2(av, cv, ac);
            bcd = fma2(bv, cv, bcd);
        }
        float s1 = log_scale(sS1[tid]);
        float s2 = log_scale(sS2[tid]);
        float ss1 = s1 * s1 * hsum2(aa);
        float ss2 = s2 * s2 * hsum2(bb);
        float d12 = s1 * s2 * hsum2(ab);
        float d1c = s1 * hsum2(ac);
        float d2c = s2 * hsum2(bcd);
        float fa, fb, fc;
        concat_coefs(ss1, ss2, d12, d1c, d2c, bc2, fa, fb, fc);
        fa *= s1; fb *= s2;                         // fold logmap scales
        const u64 fa2 = pk2(fa, fa), fb2 = pk2(fb, fb), fc2 = pk2(fc, fc);
#pragma unroll
        for (int j = 0; j < 32; ++j) {
            u64 av = A[j * 128 + tid], bv = B[j * 128 + tid];
            A[j * 128 + tid] = fma2(fa2, av, fma2(fb2, bv, mul2(fc2, bcp[j])));
        }
    }
    __syncthreads();

    // ---- S4: B = A @ W0 ----
    matvec_stage<64, 64>(A, cW0, B, w, lane);
    __syncthreads();

    // ---- S5: layer-0 chain (per row); B <- fg*B + fd*b0 ----
    {
        const u64* b0p = reinterpret_cast<const u64*>(cb0);
        u64 aa = 0, ad = 0;
#pragma unroll
        for (int j = 0; j < 32; ++j) {
            u64 bv = B[j * 128 + tid];
            aa = fma2(bv, bv, aa);
            ad = fma2(bv, b0p[j], ad);
        }
        float fg, fd;
        layer_coefs(hsum2(aa), hsum2(ad), b0sq, fg, fd);
        const u64 g2 = pk2(fg, fg), d2 = pk2(fd, fd);
#pragma unroll
        for (int j = 0; j < 32; ++j) {
            u64 bv = B[j * 128 + tid];
            B[j * 128 + tid] = fma2(g2, bv, mul2(d2, b0p[j]));
        }
    }
    __syncthreads();

    // ---- S6: A[0..16) = B @ W1 ----
    matvec_stage<64, 32>(B, cW1, A, w, lane);
    __syncthreads();

    // ---- S7: output chain + store ----
    {
        const u64* b1p = reinterpret_cast<const u64*>(cb1);
        u64 aa = 0, ad = 0;
#pragma unroll
        for (int j = 0; j < 16; ++j) {
            u64 av = A[j * 128 + tid];
            aa = fma2(av, av, aa);
            ad = fma2(av, b1p[j], ad);
        }
        float pa, pb;
        out_coefs(hsum2(aa), hsum2(ad), b1sq, pa, pb);
        float4* op = reinterpret_cast<float4*>(gout + (size_t)row * 32);
#pragma unroll
        for (int q = 0; q < 8; ++q) {
            float a0, a1, a2, a3, c0, c1, c2, c3;
            upk2(A[(2*q) * 128 + tid], a0, a1);
            upk2(A[(2*q+1) * 128 + tid], a2, a3);
            upk2(b1p[2*q],   c0, c1);
            upk2(b1p[2*q+1], c2, c3);
            op[q] = make_float4(fmaf(pa, a0, pb * c0), fmaf(pa, a1, pb * c1),
                                fmaf(pa, a2, pb * c2), fmaf(pa, a3, pb * c3));
        }
    }
}

// ---------------------------------------------------------------------------
// launch
// ---------------------------------------------------------------------------
extern "C" void kernel_launch(void* const* d_in, const int* in_sizes, int n_in,
                              void* d_out, int out_size)
{
    const float* x1 = (const float*)d_in[0];
    const float* x2 = (const float*)d_in[1];

    cudaMemcpyToSymbolAsync(cWc1, d_in[2], 32 * 64 * sizeof(float), 0, cudaMemcpyDeviceToDevice);
    cudaMemcpyToSymbolAsync(cWc2, d_in[3], 32 * 64 * sizeof(float), 0, cudaMemcpyDeviceToDevice);
    cudaMemcpyToSymbolAsync(cbc,  d_in[4], 64 * sizeof(float),      0, cudaMemcpyDeviceToDevice);
    cudaMemcpyToSymbolAsync(cW0,  d_in[5], 64 * 64 * sizeof(float), 0, cudaMemcpyDeviceToDevice);
    cudaMemcpyToSymbolAsync(cb0,  d_in[6], 64 * sizeof(float),      0, cudaMemcpyDeviceToDevice);
    cudaMemcpyToSymbolAsync(cW1,  d_in[7], 64 * 32 * sizeof(float), 0, cudaMemcpyDeviceToDevice);
    cudaMemcpyToSymbolAsync(cb1,  d_in[8], 32 * sizeof(float),      0, cudaMemcpyDeviceToDevice);

    // smem: 80*128 u64 + 256 floats = 81920 + 1024 = 82944 bytes -> 2 CTAs/SM
    const int smem_bytes = 80 * 128 * 8 + 256 * 4;
    cudaFuncSetAttribute(poincare_mlp_kernel,
                         cudaFuncAttributeMaxDynamicSharedMemorySize, smem_bytes);

    float* out = (float*)d_out;
    const int N = in_sizes[0] / 32;
    const int blocks = (N + 127) / 128;
    poincare_mlp_kernel<<<blocks, 128, smem_bytes>>>(x1, x2, out, N);
}

// round 13
// speedup vs baseline: 1.7600x; 1.0045x over previous
#include <cuda_runtime.h>
#include <stdint.h>
#include <math.h>

#define POINCARE_BOUND 0.99999f
typedef unsigned long long u64;

// ---------------------------------------------------------------------------
// weights in constant memory (LDC class) AND shared memory (LDS class).
// biases constant for everyone (tiny).
// ---------------------------------------------------------------------------
__constant__ __align__(16) float cWc1[32 * 64];
__constant__ __align__(16) float cWc2[32 * 64];
__constant__ __align__(16) float cW0 [64 * 64];
__constant__ __align__(16) float cW1 [64 * 32];
__constant__ __align__(16) float cbc [64];
__constant__ __align__(16) float cb0 [64];
__constant__ __align__(16) float cb1 [32];

// smem float offsets
#define SOFF_WC1 0
#define SOFF_WC2 2048
#define SOFF_W0  4096
#define SOFF_W1  8192

// ---------------------------------------------------------------------------
// packed f32x2 primitives
// ---------------------------------------------------------------------------
__device__ __forceinline__ u64 pk2(float lo, float hi) {
    u64 r; asm("mov.b64 %0, {%1, %2};" : "=l"(r) : "f"(lo), "f"(hi)); return r;
}
__device__ __forceinline__ void upk2(u64 v, float& lo, float& hi) {
    asm("mov.b64 {%0, %1}, %2;" : "=f"(lo), "=f"(hi) : "l"(v));
}
__device__ __forceinline__ u64 fma2(u64 a, u64 b, u64 c) {
    u64 d; asm("fma.rn.f32x2 %0, %1, %2, %3;" : "=l"(d) : "l"(a), "l"(b), "l"(c)); return d;
}
__device__ __forceinline__ u64 mul2(u64 a, u64 b) {
    u64 d; asm("mul.rn.f32x2 %0, %1, %2;" : "=l"(d) : "l"(a), "l"(b)); return d;
}
__device__ __forceinline__ float hsum2(u64 v) {
    float lo, hi; upk2(v, lo, hi); return lo + hi;
}
__device__ __forceinline__ uint32_t smem_u32(const void* p) {
    uint32_t a;
    asm("{ .reg .u64 t; cvta.to.shared.u64 t, %1; cvt.u32.u64 %0, t; }" : "=r"(a) : "l"(p));
    return a;
}
__device__ __forceinline__ void lds128(uint32_t addr, u64& a, u64& b) {
    asm volatile("ld.shared.v2.b64 {%0, %1}, [%2];" : "=l"(a), "=l"(b) : "r"(addr));
}

// ---------------------------------------------------------------------------
// fast scalar math (MUFU approx)
// ---------------------------------------------------------------------------
__device__ __forceinline__ float rcpf(float x)  { float r; asm("rcp.approx.f32 %0, %1;"  : "=f"(r) : "f"(x)); return r; }
__device__ __forceinline__ float sqrtfa(float x){ float r; asm("sqrt.approx.f32 %0, %1;" : "=f"(r) : "f"(x)); return r; }
__device__ __forceinline__ float lg2fa(float x) { float r; asm("lg2.approx.f32 %0, %1;"  : "=f"(r) : "f"(x)); return r; }
__device__ __forceinline__ float ex2fa(float x) { float r; asm("ex2.approx.f32 %0, %1;"  : "=f"(r) : "f"(x)); return r; }

__device__ __forceinline__ float log_scale(float ss) {    // atanh(min(n,B))/n
    float n = fmaxf(sqrtfa(ss), 1e-15f);
    float m = fminf(n, POINCARE_BOUND);
    float r = (1.f + m) * rcpf(1.f - m);
    return (0.34657359f * lg2fa(r)) * rcpf(n);
}
__device__ __forceinline__ float exp_scale(float ss) {     // tanh(n)/n
    float n = fmaxf(sqrtfa(ss), 1e-15f);
    float e = ex2fa(n * -2.8853901f);
    return ((1.f - e) * rcpf(1.f + e)) * rcpf(n);
}

// ---------------------------------------------------------------------------
// packed vector ops
// ---------------------------------------------------------------------------
template<int D2>
__device__ __forceinline__ float ssum2(const u64* v) {
    u64 a = 0ull;
#pragma unroll
    for (int i = 0; i < D2; ++i) a = fma2(v[i], v[i], a);
    return hsum2(a);
}
template<int D2>
__device__ __forceinline__ void scale2(u64* v, float s) {
    const u64 s2 = pk2(s, s);
#pragma unroll
    for (int i = 0; i < D2; ++i) v[i] = mul2(v[i], s2);
}
template<int D2>
__device__ __forceinline__ void logmap0p(u64* v) { scale2<D2>(v, log_scale(ssum2<D2>(v))); }
template<int D2>
__device__ __forceinline__ void expmap0p(u64* v) { scale2<D2>(v, exp_scale(ssum2<D2>(v))); }

template<int D2>
__device__ __forceinline__ void mobius_addp(u64* x, const u64* y) {
    u64 ax = 0ull, ay = 0ull, axy = 0ull;
#pragma unroll
    for (int i = 0; i < D2; ++i) {
        u64 yi = y[i];
        ax  = fma2(x[i], x[i], ax);
        ay  = fma2(yi,  yi,  ay);
        axy = fma2(x[i], yi, axy);
    }
    float x2 = hsum2(ax), y2 = hsum2(ay), xy = hsum2(axy);
    float a   = 1.f + 2.f * xy + y2;
    float b   = 1.f - x2;
    float inv = rcpf(fmaxf(1.f + 2.f * xy + x2 * y2, 1e-15f));
    const u64 a2 = pk2(a * inv, a * inv);
    const u64 b2 = pk2(b * inv, b * inv);
#pragma unroll
    for (int i = 0; i < D2; ++i)
        x[i] = fma2(b2, y[i], mul2(a2, x[i]));
}

// constant-port matvec (round-4 form)
template<int IN, int OUT, int CH>
__device__ __forceinline__ void mvC(const u64* v2, const float* cW, u64* o2) {
#pragma unroll
    for (int c0 = 0; c0 < OUT; c0 += CH) {
        u64 acc[CH / 2];
#pragma unroll
        for (int j = 0; j < CH / 2; ++j) acc[j] = 0ull;
#pragma unroll
        for (int k2 = 0; k2 < IN / 2; ++k2) {
            float lo, hi; upk2(v2[k2], lo, hi);
            const u64 va = pk2(lo, lo), vb = pk2(hi, hi);
            const ulonglong2* w0 = reinterpret_cast<const ulonglong2*>(cW + (2 * k2)     * OUT + c0);
            const ulonglong2* w1 = reinterpret_cast<const ulonglong2*>(cW + (2 * k2 + 1) * OUT + c0);
#pragma unroll
            for (int j = 0; j < CH / 4; ++j) {
                ulonglong2 wa = w0[j];
                acc[2 * j]     = fma2(va, wa.x, acc[2 * j]);
                acc[2 * j + 1] = fma2(va, wa.y, acc[2 * j + 1]);
                ulonglong2 wb = w1[j];
                acc[2 * j]     = fma2(vb, wb.x, acc[2 * j]);
                acc[2 * j + 1] = fma2(vb, wb.y, acc[2 * j + 1]);
            }
        }
#pragma unroll
        for (int j = 0; j < CH / 2; ++j) o2[c0 / 2 + j] = acc[j];
    }
}

// shared-port matvec (explicit LDS.128, warp-uniform broadcast addresses)
template<int IN, int OUT, int CH>
__device__ __forceinline__ void mvS(const u64* v2, uint32_t sbase, u64* o2) {
#pragma unroll
    for (int c0 = 0; c0 < OUT; c0 += CH) {
        u64 acc[CH / 2];
#pragma unroll
        for (int j = 0; j < CH / 2; ++j) acc[j] = 0ull;
#pragma unroll
        for (int k2 = 0; k2 < IN / 2; ++k2) {
            float lo, hi; upk2(v2[k2], lo, hi);
            const u64 va = pk2(lo, lo), vb = pk2(hi, hi);
            const uint32_t r0 = sbase + ((2 * k2)     * OUT + c0) * 4;
            const uint32_t r1 = sbase + ((2 * k2 + 1) * OUT + c0) * 4;
#pragma unroll
            for (int j = 0; j < CH / 4; ++j) {
                u64 wa0, wa1, wb0, wb1;
                lds128(r0 + j * 16, wa0, wa1);
                acc[2 * j]     = fma2(va, wa0, acc[2 * j]);
                acc[2 * j + 1] = fma2(va, wa1, acc[2 * j + 1]);
                lds128(r1 + j * 16, wb0, wb1);
                acc[2 * j]     = fma2(vb, wb0, acc[2 * j]);
                acc[2 * j + 1] = fma2(vb, wb1, acc[2 * j + 1]);
            }
        }
#pragma unroll
        for (int j = 0; j < CH / 2; ++j) o2[c0 / 2 + j] = acc[j];
    }
}

// load one 32-wide row, pack, apply logmap0
__device__ __forceinline__ void load_log32p(const float* __restrict__ gx, int row, u64* v2) {
    const float4* xp = reinterpret_cast<const float4*>(gx + (size_t)row * 32);
    u64 a = 0ull;
#pragma unroll
    for (int i = 0; i < 8; ++i) {
        float4 v = xp[i];
        u64 p0 = pk2(v.x, v.y), p1 = pk2(v.z, v.w);
        v2[2 * i] = p0; v2[2 * i + 1] = p1;
        a = fma2(p0, p0, a);
        a = fma2(p1, p1, a);
    }
    scale2<16>(v2, log_scale(hsum2(a)));
}

// full row pipeline, weight source selected at compile time per class
template<bool USE_SMEM>
__device__ __forceinline__ void process_row(const float* __restrict__ gx1,
                                            const float* __restrict__ gx2,
                                            float* __restrict__ gout,
                                            int row, uint32_t sb)
{
    u64 u2[16];
    u64 h1[32], h2[32];

    // ---- branch 1
    load_log32p(gx1, row, u2);
    if (USE_SMEM) mvS<32, 64, 32>(u2, sb + SOFF_WC1 * 4, h1);
    else          mvC<32, 64, 32>(u2, cWc1, h1);
    expmap0p<32>(h1);

    // ---- branch 2
    load_log32p(gx2, row, u2);
    if (USE_SMEM) mvS<32, 64, 32>(u2, sb + SOFF_WC2 * 4, h2);
    else          mvC<32, 64, 32>(u2, cWc2, h2);
    expmap0p<32>(h2);

    // ---- concat
    mobius_addp<32>(h1, h2);
    mobius_addp<32>(h1, reinterpret_cast<const u64*>(cbc));

    // ---- layer 0
    logmap0p<32>(h1);
    if (USE_SMEM) mvS<64, 64, 32>(h1, sb + SOFF_W0 * 4, h2);
    else          mvC<64, 64, 32>(h1, cW0, h2);
    expmap0p<32>(h2);
    mobius_addp<32>(h2, reinterpret_cast<const u64*>(cb0));

    // ---- layer 1
    logmap0p<32>(h2);
    u64 o2[16];
    if (USE_SMEM) mvS<64, 32, 32>(h2, sb + SOFF_W1 * 4, o2);
    else          mvC<64, 32, 32>(h2, cW1, o2);
    expmap0p<16>(o2);
    mobius_addp<16>(o2, reinterpret_cast<const u64*>(cb1));

    float4* op = reinterpret_cast<float4*>(gout + (size_t)row * 32);
#pragma unroll
    for (int i = 0; i < 8; ++i) {
        float x, y, z, w;
        upk2(o2[2 * i],     x, y);
        upk2(o2[2 * i + 1], z, w);
        op[i] = make_float4(x, y, z, w);
    }
}

// ---------------------------------------------------------------------------
// kernel: block=256. warps 0-3 use LDC weights, warps 4-7 use LDS weights.
// Per SMSP (wid%4): 2 LDC-class + 2 LDS-class warps -> both ports concurrent.
// ---------------------------------------------------------------------------
__global__ void __launch_bounds__(256, 2)
poincare_mlp_kernel(const float* __restrict__ gx1,
                    const float* __restrict__ gx2,
                    const float* __restrict__ gWc1,
                    const float* __restrict__ gWc2,
                    const float* __restrict__ gW0,
                    const float* __restrict__ gW1,
                    float* __restrict__ gout,
                    int N)
{
    __shared__ __align__(16) float sW[10240];   // Wc1|Wc2|W0|W1 = 40KB

    {   // cooperative fill: 2560 float4 / 256 threads = 10 each
        float4* s = reinterpret_cast<float4*>(sW);
        const int t = threadIdx.x;
        const float4* g1 = reinterpret_cast<const float4*>(gWc1);
        const float4* g2 = reinterpret_cast<const float4*>(gWc2);
        const float4* g0 = reinterpret_cast<const float4*>(gW0);
        const float4* g3 = reinterpret_cast<const float4*>(gW1);
#pragma unroll
        for (int i = 0; i < 2; ++i) s[SOFF_WC1/4 + t + 256*i] = g1[t + 256*i];
#pragma unroll
        for (int i = 0; i < 2; ++i) s[SOFF_WC2/4 + t + 256*i] = g2[t + 256*i];
#pragma unroll
        for (int i = 0; i < 4; ++i) s[SOFF_W0/4  + t + 256*i] = g0[t + 256*i];
#pragma unroll
        for (int i = 0; i < 2; ++i) s[SOFF_W1/4  + t + 256*i] = g3[t + 256*i];
    }
    __syncthreads();
    const uint32_t sb = smem_u32(sW);

    int row = blockIdx.x * 256 + threadIdx.x;
    row = row < N ? row : N - 1;

    if ((threadIdx.x >> 5) < 4)
        process_row<false>(gx1, gx2, gout, row, sb);   // LDC class
    else
        process_row<true>(gx1, gx2, gout, row, sb);    // LDS class
}

// ---------------------------------------------------------------------------
// launch
// ---------------------------------------------------------------------------
extern "C" void kernel_launch(void* const* d_in, const int* in_sizes, int n_in,
                              void* d_out, int out_size)
{
    const float* x1  = (const float*)d_in[0];
    const float* x2  = (const float*)d_in[1];
    const float* Wc1 = (const float*)d_in[2];
    const float* Wc2 = (const float*)d_in[3];
    const float* W0  = (const float*)d_in[5];
    const float* W1  = (const float*)d_in[7];

    cudaMemcpyToSymbolAsync(cWc1, d_in[2], 32 * 64 * sizeof(float), 0, cudaMemcpyDeviceToDevice);
    cudaMemcpyToSymbolAsync(cWc2, d_in[3], 32 * 64 * sizeof(float), 0, cudaMemcpyDeviceToDevice);
    cudaMemcpyToSymbolAsync(cbc,  d_in[4], 64 * sizeof(float),      0, cudaMemcpyDeviceToDevice);
    cudaMemcpyToSymbolAsync(cW0,  d_in[5], 64 * 64 * sizeof(float), 0, cudaMemcpyDeviceToDevice);
    cudaMemcpyToSymbolAsync(cb0,  d_in[6], 64 * sizeof(float),      0, cudaMemcpyDeviceToDevice);
    cudaMemcpyToSymbolAsync(cW1,  d_in[7], 64 * 32 * sizeof(float), 0, cudaMemcpyDeviceToDevice);
    cudaMemcpyToSymbolAsync(cb1,  d_in[8], 32 * sizeof(float),      0, cudaMemcpyDeviceToDevice);

    float* out = (float*)d_out;
    const int N = in_sizes[0] / 32;
    const int blocks = (N + 255) / 256;
    poincare_mlp_kernel<<<blocks, 256>>>(x1, x2, Wc1, Wc2, W0, W1, out, N);
}

// round 14
// speedup vs baseline: 2.1098x; 1.1987x over previous
#include <cuda_runtime.h>
#include <stdint.h>
#include <math.h>

#define POINCARE_BOUND 0.99999f
typedef unsigned long long u64;

// ---------------------------------------------------------------------------
// Weight placement: every matrix is split column-wise in half.
//   low half  -> __constant__ (LDC.128, per-SMSP port, floor 8)
//   high half -> __shared__   (LDS.128 broadcast, SM-wide L1, ~2.5 cyc)
// Both halves are loaded in the SAME k-iteration -> ports run concurrently.
// ---------------------------------------------------------------------------
__constant__ __align__(16) float cWc1[32 * 64];
__constant__ __align__(16) float cWc2[32 * 64];
__constant__ __align__(16) float cW0 [64 * 64];
__constant__ __align__(16) float cW1 [64 * 32];
__constant__ __align__(16) float cbc [64];
__constant__ __align__(16) float cb0 [64];
__constant__ __align__(16) float cb1 [32];

// smem float offsets of the high-half copies (row-major, stride = OUT/2)
#define SOFF_WC1H 0        // 32 x 32
#define SOFF_WC2H 1024     // 32 x 32
#define SOFF_W0H  2048     // 64 x 32
#define SOFF_W1H  4096     // 64 x 16
#define SMEM_FLOATS 5120   // 20 KB

// ---------------------------------------------------------------------------
// packed f32x2 primitives
// ---------------------------------------------------------------------------
__device__ __forceinline__ u64 pk2(float lo, float hi) {
    u64 r; asm("mov.b64 %0, {%1, %2};" : "=l"(r) : "f"(lo), "f"(hi)); return r;
}
__device__ __forceinline__ void upk2(u64 v, float& lo, float& hi) {
    asm("mov.b64 {%0, %1}, %2;" : "=f"(lo), "=f"(hi) : "l"(v));
}
__device__ __forceinline__ u64 fma2(u64 a, u64 b, u64 c) {
    u64 d; asm("fma.rn.f32x2 %0, %1, %2, %3;" : "=l"(d) : "l"(a), "l"(b), "l"(c)); return d;
}
__device__ __forceinline__ u64 mul2(u64 a, u64 b) {
    u64 d; asm("mul.rn.f32x2 %0, %1, %2;" : "=l"(d) : "l"(a), "l"(b)); return d;
}
__device__ __forceinline__ float hsum2(u64 v) {
    float lo, hi; upk2(v, lo, hi); return lo + hi;
}
__device__ __forceinline__ uint32_t smem_u32(const void* p) {
    uint32_t a;
    asm("{ .reg .u64 t; cvta.to.shared.u64 t, %1; cvt.u32.u64 %0, t; }" : "=r"(a) : "l"(p));
    return a;
}
__device__ __forceinline__ void lds128(uint32_t addr, u64& a, u64& b) {
    asm volatile("ld.shared.v2.b64 {%0, %1}, [%2];" : "=l"(a), "=l"(b) : "r"(addr));
}

// ---------------------------------------------------------------------------
// fast scalar math (MUFU approx; operand norms are O(1))
// ---------------------------------------------------------------------------
__device__ __forceinline__ float rcpf(float x)  { float r; asm("rcp.approx.f32 %0, %1;"  : "=f"(r) : "f"(x)); return r; }
__device__ __forceinline__ float sqrtfa(float x){ float r; asm("sqrt.approx.f32 %0, %1;" : "=f"(r) : "f"(x)); return r; }
__device__ __forceinline__ float lg2fa(float x) { float r; asm("lg2.approx.f32 %0, %1;"  : "=f"(r) : "f"(x)); return r; }
__device__ __forceinline__ float ex2fa(float x) { float r; asm("ex2.approx.f32 %0, %1;"  : "=f"(r) : "f"(x)); return r; }

__device__ __forceinline__ float log_scale(float ss) {    // atanh(min(n,B))/n
    float n = fmaxf(sqrtfa(ss), 1e-15f);
    float m = fminf(n, POINCARE_BOUND);
    float r = (1.f + m) * rcpf(1.f - m);
    return (0.34657359f * lg2fa(r)) * rcpf(n);
}
__device__ __forceinline__ float exp_scale(float ss) {     // tanh(n)/n
    float n = fmaxf(sqrtfa(ss), 1e-15f);
    float e = ex2fa(n * -2.8853901f);
    return ((1.f - e) * rcpf(1.f + e)) * rcpf(n);
}

// ---------------------------------------------------------------------------
// packed vector ops
// ---------------------------------------------------------------------------
template<int D2>
__device__ __forceinline__ float ssum2(const u64* v) {
    u64 a = 0ull;
#pragma unroll
    for (int i = 0; i < D2; ++i) a = fma2(v[i], v[i], a);
    return hsum2(a);
}
template<int D2>
__device__ __forceinline__ void scale2(u64* v, float s) {
    const u64 s2 = pk2(s, s);
#pragma unroll
    for (int i = 0; i < D2; ++i) v[i] = mul2(v[i], s2);
}
template<int D2>
__device__ __forceinline__ void logmap0p(u64* v) { scale2<D2>(v, log_scale(ssum2<D2>(v))); }
template<int D2>
__device__ __forceinline__ void expmap0p(u64* v) { scale2<D2>(v, exp_scale(ssum2<D2>(v))); }

template<int D2>
__device__ __forceinline__ void mobius_addp(u64* x, const u64* y) {
    u64 ax = 0ull, ay = 0ull, axy = 0ull;
#pragma unroll
    for (int i = 0; i < D2; ++i) {
        u64 yi = y[i];
        ax  = fma2(x[i], x[i], ax);
        ay  = fma2(yi,  yi,  ay);
        axy = fma2(x[i], yi, axy);
    }
    float x2 = hsum2(ax), y2 = hsum2(ay), xy = hsum2(axy);
    float a   = 1.f + 2.f * xy + y2;
    float b   = 1.f - x2;
    float inv = rcpf(fmaxf(1.f + 2.f * xy + x2 * y2, 1e-15f));
    const u64 a2 = pk2(a * inv, a * inv);
    const u64 b2 = pk2(b * inv, b * inv);
#pragma unroll
    for (int i = 0; i < D2; ++i)
        x[i] = fma2(b2, y[i], mul2(a2, x[i]));
}

// ---------------------------------------------------------------------------
// mixed-port matvec: o2[OUT/2] = v2[IN/2] @ W[IN][OUT]
// For each 16-col chunk pair: cols [c0,c0+16) from __constant__ and cols
// [HALF+c0, HALF+c0+16) from shared, loaded in the SAME k2 iteration.
// sW points at the matrix's high-half copy (row stride HALF floats).
// ---------------------------------------------------------------------------
template<int IN, int OUT>
__device__ __forceinline__ void mvMix(const u64* v2, const float* cW,
                                      uint32_t sW, u64* o2) {
    constexpr int HALF = OUT / 2;
#pragma unroll
    for (int c0 = 0; c0 < HALF; c0 += 16) {
        u64 accC[8], accS[8];
#pragma unroll
        for (int j = 0; j < 8; ++j) { accC[j] = 0ull; accS[j] = 0ull; }
#pragma unroll
        for (int k2 = 0; k2 < IN / 2; ++k2) {
            float lo, hi; upk2(v2[k2], lo, hi);
            const u64 va = pk2(lo, lo), vb = pk2(hi, hi);
            const ulonglong2* wc0 = reinterpret_cast<const ulonglong2*>(cW + (2*k2)   * OUT + c0);
            const ulonglong2* wc1 = reinterpret_cast<const ulonglong2*>(cW + (2*k2+1) * OUT + c0);
            const uint32_t rs0 = sW + ((2*k2)   * HALF + c0) * 4;
            const uint32_t rs1 = sW + ((2*k2+1) * HALF + c0) * 4;
#pragma unroll
            for (int j = 0; j < 4; ++j) {
                ulonglong2 wa = wc0[j];                      // LDC, k row
                accC[2*j]   = fma2(va, wa.x, accC[2*j]);
                accC[2*j+1] = fma2(va, wa.y, accC[2*j+1]);
                u64 s0, s1;
                lds128(rs0 + j * 16, s0, s1);                // LDS, k row
                accS[2*j]   = fma2(va, s0, accS[2*j]);
                accS[2*j+1] = fma2(va, s1, accS[2*j+1]);
                ulonglong2 wb = wc1[j];                      // LDC, k+1 row
                accC[2*j]   = fma2(vb, wb.x, accC[2*j]);
                accC[2*j+1] = fma2(vb, wb.y, accC[2*j+1]);
                u64 t0, t1;
                lds128(rs1 + j * 16, t0, t1);                // LDS, k+1 row
                accS[2*j]   = fma2(vb, t0, accS[2*j]);
                accS[2*j+1] = fma2(vb, t1, accS[2*j+1]);
            }
        }
#pragma unroll
        for (int j = 0; j < 8; ++j) {
            o2[c0 / 2 + j]          = accC[j];
            o2[(HALF + c0) / 2 + j] = accS[j];
        }
    }
}

// load one 32-wide row, pack, apply logmap0
__device__ __forceinline__ void load_log32p(const float* __restrict__ gx, int row, u64* v2) {
    const float4* xp = reinterpret_cast<const float4*>(gx + (size_t)row * 32);
    u64 a = 0ull;
#pragma unroll
    for (int i = 0; i < 8; ++i) {
        float4 v = xp[i];
        u64 p0 = pk2(v.x, v.y), p1 = pk2(v.z, v.w);
        v2[2 * i] = p0; v2[2 * i + 1] = p1;
        a = fma2(p0, p0, a);
        a = fma2(p1, p1, a);
    }
    scale2<16>(v2, log_scale(hsum2(a)));
}

// ---------------------------------------------------------------------------
// kernel: one thread per row; every matvec drives LDC and LDS concurrently
// ---------------------------------------------------------------------------
__global__ void __launch_bounds__(128, 4)
poincare_mlp_kernel(const float* __restrict__ gx1,
                    const float* __restrict__ gx2,
                    const float* __restrict__ gWc1,
                    const float* __restrict__ gWc2,
                    const float* __restrict__ gW0,
                    const float* __restrict__ gW1,
                    float* __restrict__ gout,
                    int N)
{
    __shared__ __align__(16) float sW[SMEM_FLOATS];

    {   // stage high-half columns into smem (vectorized, once per CTA)
        float4* s = reinterpret_cast<float4*>(sW);
        const float4* g1 = reinterpret_cast<const float4*>(gWc1);
        const float4* g2 = reinterpret_cast<const float4*>(gWc2);
        const float4* g0 = reinterpret_cast<const float4*>(gW0);
        const float4* g3 = reinterpret_cast<const float4*>(gW1);
        const int t = threadIdx.x;
        // Wc1 high half: 32 rows x 8 float4 (cols 32..63) = 256 float4
        for (int i = t; i < 256; i += 128) {
            int r = i >> 3, q = i & 7;
            s[SOFF_WC1H / 4 + i] = g1[r * 16 + 8 + q];
            s[SOFF_WC2H / 4 + i] = g2[r * 16 + 8 + q];
        }
        // W0 high half: 64 rows x 8 float4 = 512 float4
        for (int i = t; i < 512; i += 128) {
            int r = i >> 3, q = i & 7;
            s[SOFF_W0H / 4 + i] = g0[r * 16 + 8 + q];
        }
        // W1 high half: 64 rows x 4 float4 (cols 16..31) = 256 float4
        for (int i = t; i < 256; i += 128) {
            int r = i >> 2, q = i & 3;
            s[SOFF_W1H / 4 + i] = g3[r * 8 + 4 + q];
        }
    }
    __syncthreads();
    const uint32_t sb = smem_u32(sW);

    const int row = blockIdx.x * 128 + threadIdx.x;
    if (row >= N) return;

    u64 u2[16];
    u64 h1[32], h2[32];

    // ---- branch 1: h1 = expmap0(logmap0(x1) @ Wc1)
    load_log32p(gx1, row, u2);
    mvMix<32, 64>(u2, cWc1, sb + SOFF_WC1H * 4, h1);
    expmap0p<32>(h1);

    // ---- branch 2: h2 = expmap0(logmap0(x2) @ Wc2)
    load_log32p(gx2, row, u2);
    mvMix<32, 64>(u2, cWc2, sb + SOFF_WC2H * 4, h2);
    expmap0p<32>(h2);

    // ---- h = mobius_add(mobius_add(h1, h2), bc)
    mobius_addp<32>(h1, h2);
    mobius_addp<32>(h1, reinterpret_cast<const u64*>(cbc));

    // ---- layer 0: mobius_add(expmap0(logmap0(h) @ W0), b0)
    logmap0p<32>(h1);
    mvMix<64, 64>(h1, cW0, sb + SOFF_W0H * 4, h2);
    expmap0p<32>(h2);
    mobius_addp<32>(h2, reinterpret_cast<const u64*>(cb0));

    // ---- layer 1: mobius_add(expmap0(logmap0(h) @ W1), b1)
    logmap0p<32>(h2);
    u64 o2[16];
    mvMix<64, 32>(h2, cW1, sb + SOFF_W1H * 4, o2);
    expmap0p<16>(o2);
    mobius_addp<16>(o2, reinterpret_cast<const u64*>(cb1));

    float4* op = reinterpret_cast<float4*>(gout + (size_t)row * 32);
#pragma unroll
    for (int i = 0; i < 8; ++i) {
        float x, y, z, w;
        upk2(o2[2 * i],     x, y);
        upk2(o2[2 * i + 1], z, w);
        op[i] = make_float4(x, y, z, w);
    }
}

// ---------------------------------------------------------------------------
// launch
// ---------------------------------------------------------------------------
extern "C" void kernel_launch(void* const* d_in, const int* in_sizes, int n_in,
                              void* d_out, int out_size)
{
    const float* x1  = (const float*)d_in[0];
    const float* x2  = (const float*)d_in[1];
    const float* Wc1 = (const float*)d_in[2];
    const float* Wc2 = (const float*)d_in[3];
    const float* W0  = (const float*)d_in[5];
    const float* W1  = (const float*)d_in[7];

    cudaMemcpyToSymbolAsync(cWc1, d_in[2], 32 * 64 * sizeof(float), 0, cudaMemcpyDeviceToDevice);
    cudaMemcpyToSymbolAsync(cWc2, d_in[3], 32 * 64 * sizeof(float), 0, cudaMemcpyDeviceToDevice);
    cudaMemcpyToSymbolAsync(cbc,  d_in[4], 64 * sizeof(float),      0, cudaMemcpyDeviceToDevice);
    cudaMemcpyToSymbolAsync(cW0,  d_in[5], 64 * 64 * sizeof(float), 0, cudaMemcpyDeviceToDevice);
    cudaMemcpyToSymbolAsync(cb0,  d_in[6], 64 * sizeof(float),      0, cudaMemcpyDeviceToDevice);
    cudaMemcpyToSymbolAsync(cW1,  d_in[7], 64 * 32 * sizeof(float), 0, cudaMemcpyDeviceToDevice);
    cudaMemcpyToSymbolAsync(cb1,  d_in[8], 32 * sizeof(float),      0, cudaMemcpyDeviceToDevice);

    float* out = (float*)d_out;
    const int N = in_sizes[0] / 32;
    const int blocks = (N + 127) / 128;
    poincare_mlp_kernel<<<blocks, 128>>>(x1, x2, Wc1, Wc2, W0, W1, out, N);
}

// round 15
// speedup vs baseline: 4.1636x; 1.9735x over previous
#include <cuda_runtime.h>
#include <stdint.h>
#include <math.h>

#define POINCARE_BOUND 0.99999f

// ---------------------------------------------------------------------------
// fragment storage: hi block [0,10240), lo block [10240,20480)
// per matrix: frag f = kt*NT + nt; float index = FOFF + f*64 + lane*2 + reg
// ---------------------------------------------------------------------------
#define FOFF_WC1 0
#define FOFF_WC2 2048
#define FOFF_W0  4096
#define FOFF_W1  8192
#define FRAG_HALF 10240
#define FRAG_TOTAL 20480

__device__ __align__(16) float g_frag[FRAG_TOTAL];
__device__ int g_ktab[64];
__device__ int g_ntab[64];

// ---------------------------------------------------------------------------
// fast scalar math (validated rounds 4-12)
// ---------------------------------------------------------------------------
__device__ __forceinline__ float rcpf(float x)  { float r; asm("rcp.approx.f32 %0, %1;"  : "=f"(r) : "f"(x)); return r; }
__device__ __forceinline__ float sqrtfa(float x){ float r; asm("sqrt.approx.f32 %0, %1;" : "=f"(r) : "f"(x)); return r; }
__device__ __forceinline__ float lg2fa(float x) { float r; asm("lg2.approx.f32 %0, %1;"  : "=f"(r) : "f"(x)); return r; }
__device__ __forceinline__ float ex2fa(float x) { float r; asm("ex2.approx.f32 %0, %1;"  : "=f"(r) : "f"(x)); return r; }

__device__ __forceinline__ float log_scale(float ss) {    // atanh(min(n,B))/n
    float n = fmaxf(sqrtfa(ss), 1e-15f);
    float m = fminf(n, POINCARE_BOUND);
    float r = (1.f + m) * rcpf(1.f - m);
    return (0.34657359f * lg2fa(r)) * rcpf(n);
}
__device__ __forceinline__ float exp_scale(float ss) {     // tanh(n)/n
    float n = fmaxf(sqrtfa(ss), 1e-15f);
    float e = ex2fa(n * -2.8853901f);
    return ((1.f - e) * rcpf(1.f + e)) * rcpf(n);
}
__device__ __forceinline__ void mobius_coef(float x2, float y2, float xy, float& a, float& b) {
    float inv = rcpf(fmaxf(1.f + 2.f * xy + x2 * y2, 1e-15f));
    a = (1.f + 2.f * xy + y2) * inv;
    b = (1.f - x2) * inv;
}
__device__ __forceinline__ void concat_coefs(float ss1, float ss2, float d12,
                                             float d1c, float d2c, float bc2,
                                             float& fa, float& fb, float& fc) {
    float s1 = exp_scale(ss1), s2 = exp_scale(ss2);
    float a, b; mobius_coef(s1*s1*ss1, s2*s2*ss2, s1*s2*d12, a, b);
    float p = a * s1, q = b * s2;
    float m2  = p*p*ss1 + q*q*ss2 + 2.f*p*q*d12;
    float mbc = p*d1c + q*d2c;
    float a2, b2; mobius_coef(m2, bc2, mbc, a2, b2);
    float al = a2 * p, be = a2 * q, gc = b2;
    float g2 = al*al*ss1 + be*be*ss2 + gc*gc*bc2
             + 2.f*(al*be*d12 + al*gc*d1c + be*gc*d2c);
    float sL = log_scale(g2);
    fa = sL * al; fb = sL * be; fc = sL * gc;
}
__device__ __forceinline__ void layer_coefs(float ss, float d, float bsq,
                                            float& fg, float& fd) {
    float s = exp_scale(ss);
    float a, b; mobius_coef(s*s*ss, bsq, s*d, a, b);
    float ga = a * s, de = b;
    float g2 = ga*ga*ss + de*de*bsq + 2.f*ga*de*d;
    float sL = log_scale(g2);
    fg = sL * ga; fd = sL * de;
}
__device__ __forceinline__ void out_coefs(float ss, float d, float bsq,
                                          float& pa, float& pb) {
    float s = exp_scale(ss);
    float a, b; mobius_coef(s*s*ss, bsq, s*d, a, b);
    pa = a * s; pb = b;
}

// ---------------------------------------------------------------------------
// mma primitives
// ---------------------------------------------------------------------------
__device__ __forceinline__ void mma8(float* d, const uint32_t* a, uint32_t b0, uint32_t b1) {
    asm volatile("mma.sync.aligned.m16n8k8.row.col.f32.tf32.tf32.f32 "
        "{%0,%1,%2,%3}, {%4,%5,%6,%7}, {%8,%9}, {%0,%1,%2,%3};"
        : "+f"(d[0]), "+f"(d[1]), "+f"(d[2]), "+f"(d[3])
        : "r"(a[0]), "r"(a[1]), "r"(a[2]), "r"(a[3]), "r"(b0), "r"(b1));
}
__device__ __forceinline__ uint32_t f2tf(float x) {
    uint32_t r; asm("cvt.rn.tf32.f32 %0, %1;" : "=r"(r) : "f"(x)); return r;
}
__device__ __forceinline__ void split_tf32(float x, uint32_t& h, uint32_t& l) {
    h = f2tf(x);
    l = f2tf(x - __uint_as_float(h));
}
__device__ __forceinline__ void lds_f2(uint32_t a, float& x, float& y) {
    asm volatile("ld.shared.v2.f32 {%0,%1}, [%2];" : "=f"(x), "=f"(y) : "r"(a));
}
__device__ __forceinline__ uint32_t smem_u32(const void* p) {
    uint32_t a;
    asm("{ .reg .u64 t; cvta.to.shared.u64 t, %1; cvt.u32.u64 %0, t; }" : "=r"(a) : "l"(p));
    return a;
}
__device__ __forceinline__ float qsum(float v) {
    v += __shfl_xor_sync(0xffffffffu, v, 1);
    v += __shfl_xor_sync(0xffffffffu, v, 2);
    return v;
}

// mma matvec: aF = A-frags (KT*4 floats, pre-scaled), acc = D (NT*4, zeroed)
template<int KT, int NT>
__device__ __forceinline__ void mvmma(const float* aF, uint32_t sfrag, float* acc, int lane) {
#pragma unroll
    for (int kt = 0; kt < KT; ++kt) {
        uint32_t ah[4], al[4];
#pragma unroll
        for (int j = 0; j < 4; ++j) split_tf32(aF[kt * 4 + j], ah[j], al[j]);
#pragma unroll
        for (int nt = 0; nt < NT; ++nt) {
            uint32_t fb = sfrag + (uint32_t)(((kt * NT + nt) * 64 + lane * 2) * 4);
            float bh0, bh1, bl0, bl1;
            lds_f2(fb, bh0, bh1);
            lds_f2(fb + FRAG_HALF * 4, bl0, bl1);
            float* d = acc + nt * 4;
            mma8(d, ah, __float_as_uint(bh0), __float_as_uint(bh1));
            mma8(d, al, __float_as_uint(bh0), __float_as_uint(bh1));
            mma8(d, ah, __float_as_uint(bl0), __float_as_uint(bl1));
        }
    }
}

// permute one D-layout tile (e[4]) into A-frag regs for the matching k-tile
__device__ __forceinline__ void permute_tile(const float* e, int lane, float* a) {
    int c = lane & 3;
    int s1 = (lane & ~3) | (c >> 1);
    int s2 = s1 + 2;
    float f0 = __shfl_sync(0xffffffffu, e[0], s1), f1 = __shfl_sync(0xffffffffu, e[1], s1);
    float g0 = __shfl_sync(0xffffffffu, e[0], s2), g1 = __shfl_sync(0xffffffffu, e[1], s2);
    float h0 = __shfl_sync(0xffffffffu, e[2], s1), h1 = __shfl_sync(0xffffffffu, e[3], s1);
    float i0 = __shfl_sync(0xffffffffu, e[2], s2), i1 = __shfl_sync(0xffffffffu, e[3], s2);
    bool odd = (c & 1) != 0;
    a[0] = odd ? f1 : f0;     // row lo, col 8t+c
    a[1] = odd ? h1 : h0;     // row hi, col 8t+c
    a[2] = odd ? g1 : g0;     // row lo, col 8t+c+4
    a[3] = odd ? i1 : i0;     // row hi, col 8t+c+4
}

// ---------------------------------------------------------------------------
// probe kernel: discover B-fragment (k,n) mapping with one-hot mma probes
// ---------------------------------------------------------------------------
__global__ void probe_kernel() {
    __shared__ float sd[128];
    int lane = threadIdx.x;
    // assumed A layout, values encode k+1 (exact in tf32)
    uint32_t a[4];
    a[0] = a[1] = f2tf((float)((lane & 3) + 1));
    a[2] = a[3] = f2tf((float)((lane & 3) + 5));
#pragma unroll 1
    for (int s = 0; s < 64; ++s) {
        int plane = s >> 1, preg = s & 1;
        uint32_t b0 = 0, b1 = 0;
        uint32_t one = f2tf(1.0f);
        if (lane == plane) { if (preg == 0) b0 = one; else b1 = one; }
        float d[4] = {0.f, 0.f, 0.f, 0.f};
        mma8(d, a, b0, b1);
        sd[lane * 4 + 0] = d[0]; sd[lane * 4 + 1] = d[1];
        sd[lane * 4 + 2] = d[2]; sd[lane * 4 + 3] = d[3];
        __syncwarp();
        if (lane == 0) {
            // believed D row 0: lanes 0..3, regs 0,1 hold cols 0..7
            int kk = -1, nn = -1;
            for (int q = 0; q < 4; ++q)
                for (int rg = 0; rg < 2; ++rg) {
                    float val = sd[q * 4 + rg];
                    if (val != 0.0f) { nn = 2 * q + rg; kk = (int)(val + 0.5f) - 1; }
                }
            if (kk < 0 || kk > 7) {        // fallback: canonical mapping
                kk = (plane & 3) + preg * 4;
                nn = plane >> 2;
            }
            g_ktab[s] = kk;
            g_ntab[s] = nn;
        }
        __syncwarp();
    }
}

// ---------------------------------------------------------------------------
// prep kernel: pack all 4 matrices into hi/lo tf32 fragments
// ---------------------------------------------------------------------------
__global__ void prep_frags(const float* __restrict__ Wc1, const float* __restrict__ Wc2,
                           const float* __restrict__ W0,  const float* __restrict__ W1)
{
    int idx = blockIdx.x * blockDim.x + threadIdx.x;
    if (idx >= FRAG_HALF) return;
    const float* W; int OUT; int base;
    if (idx < 2048)      { W = Wc1; OUT = 64; base = idx; }
    else if (idx < 4096) { W = Wc2; OUT = 64; base = idx - 2048; }
    else if (idx < 8192) { W = W0;  OUT = 64; base = idx - 4096; }
    else                 { W = W1;  OUT = 32; base = idx - 8192; }
    int NT   = OUT / 8;
    int frag = base >> 6;
    int slot = base & 63;          // lane*2 + reg
    int kt = frag / NT, nt = frag % NT;
    int k = kt * 8 + g_ktab[slot];
    int n = nt * 8 + g_ntab[slot];
    float w = W[k * OUT + n];
    uint32_t hb = f2tf(w);
    float hf = __uint_as_float(hb);
    g_frag[idx] = hf;
    g_frag[FRAG_HALF + idx] = __uint_as_float(f2tf(w - hf));
}

// ---------------------------------------------------------------------------
// main kernel: 4 warps x 4 iters x 16 rows = 256 rows per CTA
// ---------------------------------------------------------------------------
#define THREADS 128

__global__ void __launch_bounds__(THREADS, 2)
poincare_mma_kernel(const float* __restrict__ gx1,
                    const float* __restrict__ gx2,
                    const float* __restrict__ gbc,
                    const float* __restrict__ gb0,
                    const float* __restrict__ gb1,
                    float* __restrict__ gout,
                    int N)
{
    extern __shared__ __align__(16) float sm[];
    // stage fragments + biases
    {
        float4* s = reinterpret_cast<float4*>(sm);
        const float4* g = reinterpret_cast<const float4*>(g_frag);
        for (int i = threadIdx.x; i < FRAG_TOTAL / 4; i += THREADS) s[i] = g[i];
        if (threadIdx.x < 64)       sm[FRAG_TOTAL + threadIdx.x] = gbc[threadIdx.x];
        else if (threadIdx.x < 128) sm[FRAG_TOTAL + threadIdx.x] = gb0[threadIdx.x - 64];
        for (int i = threadIdx.x; i < 32; i += THREADS) sm[FRAG_TOTAL + 128 + i] = gb1[i];
    }
    __syncthreads();
    const uint32_t sfrag = smem_u32(sm);
    const float* sbc = sm + FRAG_TOTAL;
    const float* sb0 = sbc + 64;
    const float* sb1 = sb0 + 64;

    const int wid = threadIdx.x >> 5;
    const int lane = threadIdx.x & 31;
    const int c = lane & 3;

    // bias self-dots (once per thread)
    float bc2 = 0.f, b0sq = 0.f, b1sq = 0.f;
    for (int i = 0; i < 64; ++i) { bc2 += sbc[i] * sbc[i]; b0sq += sb0[i] * sb0[i]; }
    for (int i = 0; i < 32; ++i) b1sq += sb1[i] * sb1[i];

    // bias fragment registers (per-lane cols 8nt+2c, +1)
    float bcr[16], b0r[16], b1r[8];
#pragma unroll
    for (int nt = 0; nt < 8; ++nt) {
        bcr[nt * 2]     = sbc[nt * 8 + 2 * c];
        bcr[nt * 2 + 1] = sbc[nt * 8 + 2 * c + 1];
        b0r[nt * 2]     = sb0[nt * 8 + 2 * c];
        b0r[nt * 2 + 1] = sb0[nt * 8 + 2 * c + 1];
    }
#pragma unroll
    for (int nt = 0; nt < 4; ++nt) {
        b1r[nt * 2]     = sb1[nt * 8 + 2 * c];
        b1r[nt * 2 + 1] = sb1[nt * 8 + 2 * c + 1];
    }

#pragma unroll 1
    for (int it = 0; it < 4; ++it) {
        const int rbase = (blockIdx.x * 16 + it * 4 + wid) * 16;
        int rlo = rbase + (lane >> 2);
        int rhi = rlo + 8;
        rlo = rlo < N ? rlo : N - 1;
        rhi = rhi < N ? rhi : N - 1;

        float raw1[32], raw2[32];

        // ---- branch matvecs via mma ----
        {
            float aF[16];
            // load + logmap scale x1
            {
                const float* plo = gx1 + (size_t)rlo * 32 + c;
                const float* phi = gx1 + (size_t)rhi * 32 + c;
                float sslo = 0.f, sshi = 0.f;
#pragma unroll
                for (int t = 0; t < 4; ++t) {
                    float v0 = plo[8 * t], v2 = plo[8 * t + 4];
                    float v1 = phi[8 * t], v3 = phi[8 * t + 4];
                    aF[t * 4 + 0] = v0; aF[t * 4 + 1] = v1;
                    aF[t * 4 + 2] = v2; aF[t * 4 + 3] = v3;
                    sslo += v0 * v0 + v2 * v2;
                    sshi += v1 * v1 + v3 * v3;
                }
                float slo = log_scale(qsum(sslo));
                float shi = log_scale(qsum(sshi));
#pragma unroll
                for (int t = 0; t < 4; ++t) {
                    aF[t * 4 + 0] *= slo; aF[t * 4 + 2] *= slo;
                    aF[t * 4 + 1] *= shi; aF[t * 4 + 3] *= shi;
                }
            }
#pragma unroll
            for (int j = 0; j < 32; ++j) raw1[j] = 0.f;
            mvmma<4, 8>(aF, sfrag + FOFF_WC1 * 4, raw1, lane);

            // x2
            {
                const float* plo = gx2 + (size_t)rlo * 32 + c;
                const float* phi = gx2 + (size_t)rhi * 32 + c;
                float sslo = 0.f, sshi = 0.f;
#pragma unroll
                for (int t = 0; t < 4; ++t) {
                    float v0 = plo[8 * t], v2 = plo[8 * t + 4];
                    float v1 = phi[8 * t], v3 = phi[8 * t + 4];
                    aF[t * 4 + 0] = v0; aF[t * 4 + 1] = v1;
                    aF[t * 4 + 2] = v2; aF[t * 4 + 3] = v3;
                    sslo += v0 * v0 + v2 * v2;
                    sshi += v1 * v1 + v3 * v3;
                }
                float slo = log_scale(qsum(sslo));
                float shi = log_scale(qsum(sshi));
#pragma unroll
                for (int t = 0; t < 4; ++t) {
                    aF[t * 4 + 0] *= slo; aF[t * 4 + 2] *= slo;
                    aF[t * 4 + 1] *= shi; aF[t * 4 + 3] *= shi;
                }
            }
#pragma unroll
            for (int j = 0; j < 32; ++j) raw2[j] = 0.f;
            mvmma<4, 8>(aF, sfrag + FOFF_WC2 * 4, raw2, lane);
        }

        // ---- fused concat chain ----
        float v[32];
        {
            float aa_l = 0, bb_l = 0, ab_l = 0, ac_l = 0, bd_l = 0;
            float aa_h = 0, bb_h = 0, ab_h = 0, ac_h = 0, bd_h = 0;
#pragma unroll
            for (int nt = 0; nt < 8; ++nt) {
                float p0 = raw1[nt*4], p1 = raw1[nt*4+1], p2 = raw1[nt*4+2], p3 = raw1[nt*4+3];
                float q0 = raw2[nt*4], q1 = raw2[nt*4+1], q2 = raw2[nt*4+2], q3 = raw2[nt*4+3];
                float c0 = bcr[nt*2], c1 = bcr[nt*2+1];
                aa_l += p0*p0 + p1*p1;  aa_h += p2*p2 + p3*p3;
                bb_l += q0*q0 + q1*q1;  bb_h += q2*q2 + q3*q3;
                ab_l += p0*q0 + p1*q1;  ab_h += p2*q2 + p3*q3;
                ac_l += p0*c0 + p1*c1;  ac_h += p2*c0 + p3*c1;
                bd_l += q0*c0 + q1*c1;  bd_h += q2*c0 + q3*c1;
            }
            aa_l = qsum(aa_l); bb_l = qsum(bb_l); ab_l = qsum(ab_l);
            ac_l = qsum(ac_l); bd_l = qsum(bd_l);
            aa_h = qsum(aa_h); bb_h = qsum(bb_h); ab_h = qsum(ab_h);
            ac_h = qsum(ac_h); bd_h = qsum(bd_h);
            float fa_l, fb_l, fc_l, fa_h, fb_h, fc_h;
            concat_coefs(aa_l, bb_l, ab_l, ac_l, bd_l, bc2, fa_l, fb_l, fc_l);
            concat_coefs(aa_h, bb_h, ab_h, ac_h, bd_h, bc2, fa_h, fb_h, fc_h);
#pragma unroll
            for (int nt = 0; nt < 8; ++nt) {
                float c0 = bcr[nt*2], c1 = bcr[nt*2+1];
                v[nt*4+0] = fa_l * raw1[nt*4+0] + fb_l * raw2[nt*4+0] + fc_l * c0;
                v[nt*4+1] = fa_l * raw1[nt*4+1] + fb_l * raw2[nt*4+1] + fc_l * c1;
                v[nt*4+2] = fa_h * raw1[nt*4+2] + fb_h * raw2[nt*4+2] + fc_h * c0;
                v[nt*4+3] = fa_h * raw1[nt*4+3] + fb_h * raw2[nt*4+3] + fc_h * c1;
            }
        }

        // ---- layer 0: permute -> mma ----
        float aF2[32];
#pragma unroll
        for (int t = 0; t < 8; ++t) permute_tile(v + t * 4, lane, aF2 + t * 4);
        float raw3[32];
#pragma unroll
        for (int j = 0; j < 32; ++j) raw3[j] = 0.f;
        mvmma<8, 8>(aF2, sfrag + FOFF_W0 * 4, raw3, lane);

        // layer-0 chain -> v2 (reuse v)
        {
            float ss_l = 0, dd_l = 0, ss_h = 0, dd_h = 0;
#pragma unroll
            for (int nt = 0; nt < 8; ++nt) {
                float p0 = raw3[nt*4], p1 = raw3[nt*4+1], p2 = raw3[nt*4+2], p3 = raw3[nt*4+3];
                float c0 = b0r[nt*2], c1 = b0r[nt*2+1];
                ss_l += p0*p0 + p1*p1;  ss_h += p2*p2 + p3*p3;
                dd_l += p0*c0 + p1*c1;  dd_h += p2*c0 + p3*c1;
            }
            ss_l = qsum(ss_l); dd_l = qsum(dd_l);
            ss_h = qsum(ss_h); dd_h = qsum(dd_h);
            float fg_l, fd_l, fg_h, fd_h;
            layer_coefs(ss_l, dd_l, b0sq, fg_l, fd_l);
            layer_coefs(ss_h, dd_h, b0sq, fg_h, fd_h);
#pragma unroll
            for (int nt = 0; nt < 8; ++nt) {
                float c0 = b0r[nt*2], c1 = b0r[nt*2+1];
                v[nt*4+0] = fg_l * raw3[nt*4+0] + fd_l * c0;
                v[nt*4+1] = fg_l * raw3[nt*4+1] + fd_l * c1;
                v[nt*4+2] = fg_h * raw3[nt*4+2] + fd_h * c0;
                v[nt*4+3] = fg_h * raw3[nt*4+3] + fd_h * c1;
            }
        }

        // ---- layer 1: permute -> mma (NT=4) ----
#pragma unroll
        for (int t = 0; t < 8; ++t) permute_tile(v + t * 4, lane, aF2 + t * 4);
        float raw4[16];
#pragma unroll
        for (int j = 0; j < 16; ++j) raw4[j] = 0.f;
        mvmma<8, 4>(aF2, sfrag + FOFF_W1 * 4, raw4, lane);

        // output chain + store
        {
            float ss_l = 0, dd_l = 0, ss_h = 0, dd_h = 0;
#pragma unroll
            for (int nt = 0; nt < 4; ++nt) {
                float p0 = raw4[nt*4], p1 = raw4[nt*4+1], p2 = raw4[nt*4+2], p3 = raw4[nt*4+3];
                float c0 = b1r[nt*2], c1 = b1r[nt*2+1];
                ss_l += p0*p0 + p1*p1;  ss_h += p2*p2 + p3*p3;
                dd_l += p0*c0 + p1*c1;  dd_h += p2*c0 + p3*c1;
            }
            ss_l = qsum(ss_l); dd_l = qsum(dd_l);
            ss_h = qsum(ss_h); dd_h = qsum(dd_h);
            float pa_l, pb_l, pa_h, pb_h;
            out_coefs(ss_l, dd_l, b1sq, pa_l, pb_l);
            out_coefs(ss_h, dd_h, b1sq, pa_h, pb_h);
            float* olo = gout + (size_t)rlo * 32;
            float* ohi = gout + (size_t)rhi * 32;
#pragma unroll
            for (int nt = 0; nt < 4; ++nt) {
                float c0 = b1r[nt*2], c1 = b1r[nt*2+1];
                float2 vlo = make_float2(pa_l * raw4[nt*4+0] + pb_l * c0,
                                         pa_l * raw4[nt*4+1] + pb_l * c1);
                float2 vhi = make_float2(pa_h * raw4[nt*4+2] + pb_h * c0,
                                         pa_h * raw4[nt*4+3] + pb_h * c1);
                *reinterpret_cast<float2*>(olo + nt * 8 + 2 * c) = vlo;
                *reinterpret_cast<float2*>(ohi + nt * 8 + 2 * c) = vhi;
            }
        }
    }
}

// ---------------------------------------------------------------------------
// launch: probe -> prep -> main (sequential on stream, graph-capturable)
// ---------------------------------------------------------------------------
extern "C" void kernel_launch(void* const* d_in, const int* in_sizes, int n_in,
                              void* d_out, int out_size)
{
    const float* x1  = (const float*)d_in[0];
    const float* x2  = (const float*)d_in[1];
    const float* Wc1 = (const float*)d_in[2];
    const float* Wc2 = (const float*)d_in[3];
    const float* bc  = (const float*)d_in[4];
    const float* W0  = (const float*)d_in[5];
    const float* b0  = (const float*)d_in[6];
    const float* W1  = (const float*)d_in[7];
    const float* b1  = (const float*)d_in[8];
    float* out = (float*)d_out;

    probe_kernel<<<1, 32>>>();
    prep_frags<<<40, 256>>>(Wc1, Wc2, W0, W1);

    const int smem_bytes = FRAG_TOTAL * 4 + 160 * 4;
    static bool attr_set = false;
    if (!attr_set) {
        cudaFuncSetAttribute(poincare_mma_kernel,
                             cudaFuncAttributeMaxDynamicSharedMemorySize, smem_bytes);
        attr_set = true;
    }

    const int N = in_sizes[0] / 32;
    const int rows_per_cta = 256;
    const int blocks = (N + rows_per_cta - 1) / rows_per_cta;
    poincare_mma_kernel<<<blocks, THREADS, smem_bytes>>>(x1, x2, bc, b0, b1, out, N);
}

// round 16
// speedup vs baseline: 4.6400x; 1.1144x over previous
#include <cuda_runtime.h>
#include <stdint.h>
#include <math.h>

#define POINCARE_BOUND 0.99999f

// ---------------------------------------------------------------------------
// fragment storage: hi block [0,10240), lo block [10240,20480)
// per matrix: frag f = kt*NT + nt; float index = FOFF + f*64 + lane*2 + reg
// ---------------------------------------------------------------------------
#define FOFF_WC1 0
#define FOFF_WC2 2048
#define FOFF_W0  4096
#define FOFF_W1  8192
#define FRAG_HALF 10240
#define FRAG_TOTAL 20480

__device__ __align__(16) float g_frag[FRAG_TOTAL];
__device__ int g_ktab[64];
__device__ int g_ntab[64];

// ---------------------------------------------------------------------------
// fast scalar math (validated rounds 4-15)
// ---------------------------------------------------------------------------
__device__ __forceinline__ float rcpf(float x)  { float r; asm("rcp.approx.f32 %0, %1;"  : "=f"(r) : "f"(x)); return r; }
__device__ __forceinline__ float sqrtfa(float x){ float r; asm("sqrt.approx.f32 %0, %1;" : "=f"(r) : "f"(x)); return r; }
__device__ __forceinline__ float lg2fa(float x) { float r; asm("lg2.approx.f32 %0, %1;"  : "=f"(r) : "f"(x)); return r; }
__device__ __forceinline__ float ex2fa(float x) { float r; asm("ex2.approx.f32 %0, %1;"  : "=f"(r) : "f"(x)); return r; }

__device__ __forceinline__ float log_scale(float ss) {    // atanh(min(n,B))/n
    float n = fmaxf(sqrtfa(ss), 1e-15f);
    float m = fminf(n, POINCARE_BOUND);
    float r = (1.f + m) * rcpf(1.f - m);
    return (0.34657359f * lg2fa(r)) * rcpf(n);
}
__device__ __forceinline__ float exp_scale(float ss) {     // tanh(n)/n
    float n = fmaxf(sqrtfa(ss), 1e-15f);
    float e = ex2fa(n * -2.8853901f);
    return ((1.f - e) * rcpf(1.f + e)) * rcpf(n);
}
__device__ __forceinline__ void mobius_coef(float x2, float y2, float xy, float& a, float& b) {
    float inv = rcpf(fmaxf(1.f + 2.f * xy + x2 * y2, 1e-15f));
    a = (1.f + 2.f * xy + y2) * inv;
    b = (1.f - x2) * inv;
}
__device__ __forceinline__ void concat_coefs(float ss1, float ss2, float d12,
                                             float d1c, float d2c, float bc2,
                                             float& fa, float& fb, float& fc) {
    float s1 = exp_scale(ss1), s2 = exp_scale(ss2);
    float a, b; mobius_coef(s1*s1*ss1, s2*s2*ss2, s1*s2*d12, a, b);
    float p = a * s1, q = b * s2;
    float m2  = p*p*ss1 + q*q*ss2 + 2.f*p*q*d12;
    float mbc = p*d1c + q*d2c;
    float a2, b2; mobius_coef(m2, bc2, mbc, a2, b2);
    float al = a2 * p, be = a2 * q, gc = b2;
    float g2 = al*al*ss1 + be*be*ss2 + gc*gc*bc2
             + 2.f*(al*be*d12 + al*gc*d1c + be*gc*d2c);
    float sL = log_scale(g2);
    fa = sL * al; fb = sL * be; fc = sL * gc;
}
__device__ __forceinline__ void layer_coefs(float ss, float d, float bsq,
                                            float& fg, float& fd) {
    float s = exp_scale(ss);
    float a, b; mobius_coef(s*s*ss, bsq, s*d, a, b);
    float ga = a * s, de = b;
    float g2 = ga*ga*ss + de*de*bsq + 2.f*ga*de*d;
    float sL = log_scale(g2);
    fg = sL * ga; fd = sL * de;
}
__device__ __forceinline__ void out_coefs(float ss, float d, float bsq,
                                          float& pa, float& pb) {
    float s = exp_scale(ss);
    float a, b; mobius_coef(s*s*ss, bsq, s*d, a, b);
    pa = a * s; pb = b;
}

// ---------------------------------------------------------------------------
// mma primitives
// ---------------------------------------------------------------------------
__device__ __forceinline__ void mma8(float* d, const uint32_t* a, uint32_t b0, uint32_t b1) {
    asm volatile("mma.sync.aligned.m16n8k8.row.col.f32.tf32.tf32.f32 "
        "{%0,%1,%2,%3}, {%4,%5,%6,%7}, {%8,%9}, {%0,%1,%2,%3};"
        : "+f"(d[0]), "+f"(d[1]), "+f"(d[2]), "+f"(d[3])
        : "r"(a[0]), "r"(a[1]), "r"(a[2]), "r"(a[3]), "r"(b0), "r"(b1));
}
__device__ __forceinline__ uint32_t f2tf(float x) {
    uint32_t r; asm("cvt.rn.tf32.f32 %0, %1;" : "=r"(r) : "f"(x)); return r;
}
__device__ __forceinline__ void split_tf32(float x, uint32_t& h, uint32_t& l) {
    h = f2tf(x);
    l = f2tf(x - __uint_as_float(h));
}
__device__ __forceinline__ void lds_f2(uint32_t a, float& x, float& y) {
    asm volatile("ld.shared.v2.f32 {%0,%1}, [%2];" : "=f"(x), "=f"(y) : "r"(a));
}
__device__ __forceinline__ uint32_t smem_u32(const void* p) {
    uint32_t a;
    asm("{ .reg .u64 t; cvta.to.shared.u64 t, %1; cvt.u32.u64 %0, t; }" : "=r"(a) : "l"(p));
    return a;
}
__device__ __forceinline__ float qsum(float v) {
    v += __shfl_xor_sync(0xffffffffu, v, 1);
    v += __shfl_xor_sync(0xffffffffu, v, 2);
    return v;
}

// mma matvec: aF = A-frags (KT*4 floats, pre-scaled), acc = D (NT*4, zeroed)
template<int KT, int NT>
__device__ __forceinline__ void mvmma(const float* aF, uint32_t sfrag, float* acc, int lane) {
#pragma unroll
    for (int kt = 0; kt < KT; ++kt) {
        uint32_t ah[4], al[4];
#pragma unroll
        for (int j = 0; j < 4; ++j) split_tf32(aF[kt * 4 + j], ah[j], al[j]);
#pragma unroll
        for (int nt = 0; nt < NT; ++nt) {
            uint32_t fb = sfrag + (uint32_t)(((kt * NT + nt) * 64 + lane * 2) * 4);
            float bh0, bh1, bl0, bl1;
            lds_f2(fb, bh0, bh1);
            lds_f2(fb + FRAG_HALF * 4, bl0, bl1);
            float* d = acc + nt * 4;
            mma8(d, ah, __float_as_uint(bh0), __float_as_uint(bh1));
            mma8(d, al, __float_as_uint(bh0), __float_as_uint(bh1));
            mma8(d, ah, __float_as_uint(bl0), __float_as_uint(bl1));
        }
    }
}

// permute one D-layout tile (e[4]) into A-frag regs for the matching k-tile
__device__ __forceinline__ void permute_tile(const float* e, int lane, float* a) {
    int c = lane & 3;
    int s1 = (lane & ~3) | (c >> 1);
    int s2 = s1 + 2;
    float f0 = __shfl_sync(0xffffffffu, e[0], s1), f1 = __shfl_sync(0xffffffffu, e[1], s1);
    float g0 = __shfl_sync(0xffffffffu, e[0], s2), g1 = __shfl_sync(0xffffffffu, e[1], s2);
    float h0 = __shfl_sync(0xffffffffu, e[2], s1), h1 = __shfl_sync(0xffffffffu, e[3], s1);
    float i0 = __shfl_sync(0xffffffffu, e[2], s2), i1 = __shfl_sync(0xffffffffu, e[3], s2);
    bool odd = (c & 1) != 0;
    a[0] = odd ? f1 : f0;
    a[1] = odd ? h1 : h0;
    a[2] = odd ? g1 : g0;
    a[3] = odd ? i1 : i0;
}

// ---------------------------------------------------------------------------
// probe kernel (cheap): 8 one-hot-k probes; B slots carry slot+1 (exact tf32).
// Probe k0: A[row][k] = delta(k,k0)  ->  D[0][n] = B[k0][n] = slot+1.
// Same A/D layout assumptions as the main kernel -> self-correcting for B.
// ---------------------------------------------------------------------------
__global__ void probe_kernel() {
    __shared__ float sd[128];
    int lane = threadIdx.x;
    int c = lane & 3;
    uint32_t b0 = f2tf((float)(lane * 2 + 1));
    uint32_t b1 = f2tf((float)(lane * 2 + 2));
    uint32_t one = f2tf(1.0f);
#pragma unroll 1
    for (int k0 = 0; k0 < 8; ++k0) {
        uint32_t a[4] = {0u, 0u, 0u, 0u};
        if (c == k0)     { a[0] = one; a[1] = one; }
        if (c + 4 == k0) { a[2] = one; a[3] = one; }
        float d[4] = {0.f, 0.f, 0.f, 0.f};
        mma8(d, a, b0, b1);
        sd[lane * 4 + 0] = d[0]; sd[lane * 4 + 1] = d[1];
        sd[lane * 4 + 2] = d[2]; sd[lane * 4 + 3] = d[3];
        __syncwarp();
        if (lane < 8) {
            int n = lane;
            float val = sd[(n >> 1) * 4 + (n & 1)];   // D row 0, col n
            int s = (int)(val + 0.5f) - 1;
            if (s >= 0 && s < 64) { g_ktab[s] = k0; g_ntab[s] = n; }
        }
        __syncwarp();
    }
}

// ---------------------------------------------------------------------------
// prep kernel: pack all 4 matrices into hi/lo tf32 fragments
// ---------------------------------------------------------------------------
__global__ void prep_frags(const float* __restrict__ Wc1, const float* __restrict__ Wc2,
                           const float* __restrict__ W0,  const float* __restrict__ W1)
{
    int idx = blockIdx.x * blockDim.x + threadIdx.x;
    if (idx >= FRAG_HALF) return;
    const float* W; int OUT; int base;
    if (idx < 2048)      { W = Wc1; OUT = 64; base = idx; }
    else if (idx < 4096) { W = Wc2; OUT = 64; base = idx - 2048; }
    else if (idx < 8192) { W = W0;  OUT = 64; base = idx - 4096; }
    else                 { W = W1;  OUT = 32; base = idx - 8192; }
    int NT   = OUT / 8;
    int frag = base >> 6;
    int slot = base & 63;
    int kt = frag / NT, nt = frag % NT;
    int k = kt * 8 + g_ktab[slot];
    int n = nt * 8 + g_ntab[slot];
    float w = W[k * OUT + n];
    uint32_t hb = f2tf(w);
    float hf = __uint_as_float(hb);
    g_frag[idx] = hf;
    g_frag[FRAG_HALF + idx] = __uint_as_float(f2tf(w - hf));
}

// ---------------------------------------------------------------------------
// main kernel: 8 warps x 4 iters x 16 rows = 512 rows per CTA; 16 warps/SM
// ---------------------------------------------------------------------------
#define THREADS 256

__global__ void __launch_bounds__(THREADS, 2)
poincare_mma_kernel(const float* __restrict__ gx1,
                    const float* __restrict__ gx2,
                    const float* __restrict__ gbc,
                    const float* __restrict__ gb0,
                    const float* __restrict__ gb1,
                    float* __restrict__ gout,
                    int N)
{
    extern __shared__ __align__(16) float sm[];
    {
        float4* s = reinterpret_cast<float4*>(sm);
        const float4* g = reinterpret_cast<const float4*>(g_frag);
        for (int i = threadIdx.x; i < FRAG_TOTAL / 4; i += THREADS) s[i] = g[i];
        if (threadIdx.x < 64)       sm[FRAG_TOTAL + threadIdx.x] = gbc[threadIdx.x];
        else if (threadIdx.x < 128) sm[FRAG_TOTAL + threadIdx.x] = gb0[threadIdx.x - 64];
        else if (threadIdx.x < 160) sm[FRAG_TOTAL + threadIdx.x] = gb1[threadIdx.x - 128];
    }
    __syncthreads();
    const uint32_t sfrag = smem_u32(sm);
    const float* sbc = sm + FRAG_TOTAL;
    const float* sb0 = sbc + 64;
    const float* sb1 = sb0 + 64;

    const int wid = threadIdx.x >> 5;
    const int lane = threadIdx.x & 31;
    const int c = lane & 3;

    float bc2 = 0.f, b0sq = 0.f, b1sq = 0.f;
    for (int i = 0; i < 64; ++i) { bc2 += sbc[i] * sbc[i]; b0sq += sb0[i] * sb0[i]; }
    for (int i = 0; i < 32; ++i) b1sq += sb1[i] * sb1[i];

    float bcr[16], b0r[16], b1r[8];
#pragma unroll
    for (int nt = 0; nt < 8; ++nt) {
        bcr[nt * 2]     = sbc[nt * 8 + 2 * c];
        bcr[nt * 2 + 1] = sbc[nt * 8 + 2 * c + 1];
        b0r[nt * 2]     = sb0[nt * 8 + 2 * c];
        b0r[nt * 2 + 1] = sb0[nt * 8 + 2 * c + 1];
    }
#pragma unroll
    for (int nt = 0; nt < 4; ++nt) {
        b1r[nt * 2]     = sb1[nt * 8 + 2 * c];
        b1r[nt * 2 + 1] = sb1[nt * 8 + 2 * c + 1];
    }

#pragma unroll 1
    for (int it = 0; it < 4; ++it) {
        const int rbase = (blockIdx.x * 32 + it * 8 + wid) * 16;
        int rlo = rbase + (lane >> 2);
        int rhi = rlo + 8;
        rlo = rlo < N ? rlo : N - 1;
        rhi = rhi < N ? rhi : N - 1;

        float raw1[32], raw2[32];

        // ---- branch matvecs via mma ----
        {
            float aF[16];
            {
                const float* plo = gx1 + (size_t)rlo * 32 + c;
                const float* phi = gx1 + (size_t)rhi * 32 + c;
                float sslo = 0.f, sshi = 0.f;
#pragma unroll
                for (int t = 0; t < 4; ++t) {
                    float v0 = plo[8 * t], v2 = plo[8 * t + 4];
                    float v1 = phi[8 * t], v3 = phi[8 * t + 4];
                    aF[t * 4 + 0] = v0; aF[t * 4 + 1] = v1;
                    aF[t * 4 + 2] = v2; aF[t * 4 + 3] = v3;
                    sslo += v0 * v0 + v2 * v2;
                    sshi += v1 * v1 + v3 * v3;
                }
                float slo = log_scale(qsum(sslo));
                float shi = log_scale(qsum(sshi));
#pragma unroll
                for (int t = 0; t < 4; ++t) {
                    aF[t * 4 + 0] *= slo; aF[t * 4 + 2] *= slo;
                    aF[t * 4 + 1] *= shi; aF[t * 4 + 3] *= shi;
                }
            }
#pragma unroll
            for (int j = 0; j < 32; ++j) raw1[j] = 0.f;
            mvmma<4, 8>(aF, sfrag + FOFF_WC1 * 4, raw1, lane);

            {
                const float* plo = gx2 + (size_t)rlo * 32 + c;
                const float* phi = gx2 + (size_t)rhi * 32 + c;
                float sslo = 0.f, sshi = 0.f;
#pragma unroll
                for (int t = 0; t < 4; ++t) {
                    float v0 = plo[8 * t], v2 = plo[8 * t + 4];
                    float v1 = phi[8 * t], v3 = phi[8 * t + 4];
                    aF[t * 4 + 0] = v0; aF[t * 4 + 1] = v1;
                    aF[t * 4 + 2] = v2; aF[t * 4 + 3] = v3;
                    sslo += v0 * v0 + v2 * v2;
                    sshi += v1 * v1 + v3 * v3;
                }
                float slo = log_scale(qsum(sslo));
                float shi = log_scale(qsum(sshi));
#pragma unroll
                for (int t = 0; t < 4; ++t) {
                    aF[t * 4 + 0] *= slo; aF[t * 4 + 2] *= slo;
                    aF[t * 4 + 1] *= shi; aF[t * 4 + 3] *= shi;
                }
            }
#pragma unroll
            for (int j = 0; j < 32; ++j) raw2[j] = 0.f;
            mvmma<4, 8>(aF, sfrag + FOFF_WC2 * 4, raw2, lane);
        }

        // ---- fused concat chain; v overwrites raw1 ----
        {
            float aa_l = 0, bb_l = 0, ab_l = 0, ac_l = 0, bd_l = 0;
            float aa_h = 0, bb_h = 0, ab_h = 0, ac_h = 0, bd_h = 0;
#pragma unroll
            for (int nt = 0; nt < 8; ++nt) {
                float p0 = raw1[nt*4], p1 = raw1[nt*4+1], p2 = raw1[nt*4+2], p3 = raw1[nt*4+3];
                float q0 = raw2[nt*4], q1 = raw2[nt*4+1], q2 = raw2[nt*4+2], q3 = raw2[nt*4+3];
                float c0 = bcr[nt*2], c1 = bcr[nt*2+1];
                aa_l += p0*p0 + p1*p1;  aa_h += p2*p2 + p3*p3;
                bb_l += q0*q0 + q1*q1;  bb_h += q2*q2 + q3*q3;
                ab_l += p0*q0 + p1*q1;  ab_h += p2*q2 + p3*q3;
                ac_l += p0*c0 + p1*c1;  ac_h += p2*c0 + p3*c1;
                bd_l += q0*c0 + q1*c1;  bd_h += q2*c0 + q3*c1;
            }
            aa_l = qsum(aa_l); bb_l = qsum(bb_l); ab_l = qsum(ab_l);
            ac_l = qsum(ac_l); bd_l = qsum(bd_l);
            aa_h = qsum(aa_h); bb_h = qsum(bb_h); ab_h = qsum(ab_h);
            ac_h = qsum(ac_h); bd_h = qsum(bd_h);
            float fa_l, fb_l, fc_l, fa_h, fb_h, fc_h;
            concat_coefs(aa_l, bb_l, ab_l, ac_l, bd_l, bc2, fa_l, fb_l, fc_l);
            concat_coefs(aa_h, bb_h, ab_h, ac_h, bd_h, bc2, fa_h, fb_h, fc_h);
#pragma unroll
            for (int nt = 0; nt < 8; ++nt) {
                float c0 = bcr[nt*2], c1 = bcr[nt*2+1];
                raw1[nt*4+0] = fa_l * raw1[nt*4+0] + fb_l * raw2[nt*4+0] + fc_l * c0;
                raw1[nt*4+1] = fa_l * raw1[nt*4+1] + fb_l * raw2[nt*4+1] + fc_l * c1;
                raw1[nt*4+2] = fa_h * raw1[nt*4+2] + fb_h * raw2[nt*4+2] + fc_h * c0;
                raw1[nt*4+3] = fa_h * raw1[nt*4+3] + fb_h * raw2[nt*4+3] + fc_h * c1;
            }
        }

        // ---- layer 0: permute -> mma; raw2 becomes aF2, raw3 in fresh regs ----
        float aF2[32];
#pragma unroll
        for (int t = 0; t < 8; ++t) permute_tile(raw1 + t * 4, lane, aF2 + t * 4);
        float raw3[32];
#pragma unroll
        for (int j = 0; j < 32; ++j) raw3[j] = 0.f;
        mvmma<8, 8>(aF2, sfrag + FOFF_W0 * 4, raw3, lane);

        // layer-0 chain; v2 overwrites raw3
        {
            float ss_l = 0, dd_l = 0, ss_h = 0, dd_h = 0;
#pragma unroll
            for (int nt = 0; nt < 8; ++nt) {
                float p0 = raw3[nt*4], p1 = raw3[nt*4+1], p2 = raw3[nt*4+2], p3 = raw3[nt*4+3];
                float c0 = b0r[nt*2], c1 = b0r[nt*2+1];
                ss_l += p0*p0 + p1*p1;  ss_h += p2*p2 + p3*p3;
                dd_l += p0*c0 + p1*c1;  dd_h += p2*c0 + p3*c1;
            }
            ss_l = qsum(ss_l); dd_l = qsum(dd_l);
            ss_h = qsum(ss_h); dd_h = qsum(dd_h);
            float fg_l, fd_l, fg_h, fd_h;
            layer_coefs(ss_l, dd_l, b0sq, fg_l, fd_l);
            layer_coefs(ss_h, dd_h, b0sq, fg_h, fd_h);
#pragma unroll
            for (int nt = 0; nt < 8; ++nt) {
                float c0 = b0r[nt*2], c1 = b0r[nt*2+1];
                raw3[nt*4+0] = fg_l * raw3[nt*4+0] + fd_l * c0;
                raw3[nt*4+1] = fg_l * raw3[nt*4+1] + fd_l * c1;
                raw3[nt*4+2] = fg_h * raw3[nt*4+2] + fd_h * c0;
                raw3[nt*4+3] = fg_h * raw3[nt*4+3] + fd_h * c1;
            }
        }

        // ---- layer 1: permute -> mma (NT=4) ----
#pragma unroll
        for (int t = 0; t < 8; ++t) permute_tile(raw3 + t * 4, lane, aF2 + t * 4);
        float raw4[16];
#pragma unroll
        for (int j = 0; j < 16; ++j) raw4[j] = 0.f;
        mvmma<8, 4>(aF2, sfrag + FOFF_W1 * 4, raw4, lane);

        // output chain + store
        {
            float ss_l = 0, dd_l = 0, ss_h = 0, dd_h = 0;
#pragma unroll
            for (int nt = 0; nt < 4; ++nt) {
                float p0 = raw4[nt*4], p1 = raw4[nt*4+1], p2 = raw4[nt*4+2], p3 = raw4[nt*4+3];
                float c0 = b1r[nt*2], c1 = b1r[nt*2+1];
                ss_l += p0*p0 + p1*p1;  ss_h += p2*p2 + p3*p3;
                dd_l += p0*c0 + p1*c1;  dd_h += p2*c0 + p3*c1;
            }
            ss_l = qsum(ss_l); dd_l = qsum(dd_l);
            ss_h = qsum(ss_h); dd_h = qsum(dd_h);
            float pa_l, pb_l, pa_h, pb_h;
            out_coefs(ss_l, dd_l, b1sq, pa_l, pb_l);
            out_coefs(ss_h, dd_h, b1sq, pa_h, pb_h);
            float* olo = gout + (size_t)rlo * 32;
            float* ohi = gout + (size_t)rhi * 32;
#pragma unroll
            for (int nt = 0; nt < 4; ++nt) {
                float c0 = b1r[nt*2], c1 = b1r[nt*2+1];
                float2 vlo = make_float2(pa_l * raw4[nt*4+0] + pb_l * c0,
                                         pa_l * raw4[nt*4+1] + pb_l * c1);
                float2 vhi = make_float2(pa_h * raw4[nt*4+2] + pb_h * c0,
                                         pa_h * raw4[nt*4+3] + pb_h * c1);
                *reinterpret_cast<float2*>(olo + nt * 8 + 2 * c) = vlo;
                *reinterpret_cast<float2*>(ohi + nt * 8 + 2 * c) = vhi;
            }
        }
    }
}

// ---------------------------------------------------------------------------
// launch: probe -> prep -> main
// ---------------------------------------------------------------------------
extern "C" void kernel_launch(void* const* d_in, const int* in_sizes, int n_in,
                              void* d_out, int out_size)
{
    const float* x1  = (const float*)d_in[0];
    const float* x2  = (const float*)d_in[1];
    const float* Wc1 = (const float*)d_in[2];
    const float* Wc2 = (const float*)d_in[3];
    const float* bc  = (const float*)d_in[4];
    const float* W0  = (const float*)d_in[5];
    const float* b0  = (const float*)d_in[6];
    const float* W1  = (const float*)d_in[7];
    const float* b1  = (const float*)d_in[8];
    float* out = (float*)d_out;

    probe_kernel<<<1, 32>>>();
    prep_frags<<<40, 256>>>(Wc1, Wc2, W0, W1);

    const int smem_bytes = FRAG_TOTAL * 4 + 160 * 4;
    cudaFuncSetAttribute(poincare_mma_kernel,
                         cudaFuncAttributeMaxDynamicSharedMemorySize, smem_bytes);

    const int N = in_sizes[0] / 32;
    const int rows_per_cta = 512;
    const int blocks = (N + rows_per_cta - 1) / rows_per_cta;
    poincare_mma_kernel<<<blocks, THREADS, smem_bytes>>>(x1, x2, bc, b0, b1, out, N);
}

// round 17
// speedup vs baseline: 7.2639x; 1.5655x over previous
#include <cuda_runtime.h>
#include <stdint.h>
#include <math.h>

#define POINCARE_BOUND 0.99999f

// ---------------------------------------------------------------------------
// bf16 fragment storage (u32 units): hi block [0,5120), lo block [5120,10240)
// per matrix: frag f = kt*NT + nt; u32 index = FOFF + f*64 + lane*2 + reg
// each u32 packs 2 bf16 (half0 = low 16 bits, half1 = high)
// ---------------------------------------------------------------------------
#define FOFF_WC1 0
#define FOFF_WC2 1024
#define FOFF_W0  2048
#define FOFF_W1  4096
#define FRAG_HALF 5120
#define FRAG_TOTAL 10240

__device__ __align__(16) uint32_t g_frag[FRAG_TOTAL];
__device__ int g_ktab[128];
__device__ int g_ntab[128];

// ---------------------------------------------------------------------------
// fast scalar math (validated rounds 4-16)
// ---------------------------------------------------------------------------
__device__ __forceinline__ float rcpf(float x)  { float r; asm("rcp.approx.f32 %0, %1;"  : "=f"(r) : "f"(x)); return r; }
__device__ __forceinline__ float sqrtfa(float x){ float r; asm("sqrt.approx.f32 %0, %1;" : "=f"(r) : "f"(x)); return r; }
__device__ __forceinline__ float lg2fa(float x) { float r; asm("lg2.approx.f32 %0, %1;"  : "=f"(r) : "f"(x)); return r; }
__device__ __forceinline__ float ex2fa(float x) { float r; asm("ex2.approx.f32 %0, %1;"  : "=f"(r) : "f"(x)); return r; }

__device__ __forceinline__ float log_scale(float ss) {
    float n = fmaxf(sqrtfa(ss), 1e-15f);
    float m = fminf(n, POINCARE_BOUND);
    float r = (1.f + m) * rcpf(1.f - m);
    return (0.34657359f * lg2fa(r)) * rcpf(n);
}
__device__ __forceinline__ float exp_scale(float ss) {
    float n = fmaxf(sqrtfa(ss), 1e-15f);
    float e = ex2fa(n * -2.8853901f);
    return ((1.f - e) * rcpf(1.f + e)) * rcpf(n);
}
__device__ __forceinline__ void mobius_coef(float x2, float y2, float xy, float& a, float& b) {
    float inv = rcpf(fmaxf(1.f + 2.f * xy + x2 * y2, 1e-15f));
    a = (1.f + 2.f * xy + y2) * inv;
    b = (1.f - x2) * inv;
}
__device__ __forceinline__ void concat_coefs(float ss1, float ss2, float d12,
                                             float d1c, float d2c, float bc2,
                                             float& fa, float& fb, float& fc) {
    float s1 = exp_scale(ss1), s2 = exp_scale(ss2);
    float a, b; mobius_coef(s1*s1*ss1, s2*s2*ss2, s1*s2*d12, a, b);
    float p = a * s1, q = b * s2;
    float m2  = p*p*ss1 + q*q*ss2 + 2.f*p*q*d12;
    float mbc = p*d1c + q*d2c;
    float a2, b2; mobius_coef(m2, bc2, mbc, a2, b2);
    float al = a2 * p, be = a2 * q, gc = b2;
    float g2 = al*al*ss1 + be*be*ss2 + gc*gc*bc2
             + 2.f*(al*be*d12 + al*gc*d1c + be*gc*d2c);
    float sL = log_scale(g2);
    fa = sL * al; fb = sL * be; fc = sL * gc;
}
__device__ __forceinline__ void layer_coefs(float ss, float d, float bsq,
                                            float& fg, float& fd) {
    float s = exp_scale(ss);
    float a, b; mobius_coef(s*s*ss, bsq, s*d, a, b);
    float ga = a * s, de = b;
    float g2 = ga*ga*ss + de*de*bsq + 2.f*ga*de*d;
    float sL = log_scale(g2);
    fg = sL * ga; fd = sL * de;
}
__device__ __forceinline__ void out_coefs(float ss, float d, float bsq,
                                          float& pa, float& pb) {
    float s = exp_scale(ss);
    float a, b; mobius_coef(s*s*ss, bsq, s*d, a, b);
    pa = a * s; pb = b;
}

// ---------------------------------------------------------------------------
// bf16 mma primitives
// ---------------------------------------------------------------------------
__device__ __forceinline__ void mma16(float* d, const uint32_t* a, uint32_t b0, uint32_t b1) {
    asm volatile("mma.sync.aligned.m16n8k16.row.col.f32.bf16.bf16.f32 "
        "{%0,%1,%2,%3}, {%4,%5,%6,%7}, {%8,%9}, {%0,%1,%2,%3};"
        : "+f"(d[0]), "+f"(d[1]), "+f"(d[2]), "+f"(d[3])
        : "r"(a[0]), "r"(a[1]), "r"(a[2]), "r"(a[3]), "r"(b0), "r"(b1));
}
// pack: half0 = bf16(v0), half1 = bf16(v1)
__device__ __forceinline__ uint32_t bf16pk(float v0, float v1) {
    uint32_t r; asm("cvt.rn.bf16x2.f32 %0, %1, %2;" : "=r"(r) : "f"(v1), "f"(v0)); return r;
}
// hi/lo split of a packed pair
__device__ __forceinline__ void split2(float v0, float v1, uint32_t& h, uint32_t& l) {
    h = bf16pk(v0, v1);
    float h0 = __uint_as_float(h << 16);
    float h1 = __uint_as_float(h & 0xffff0000u);
    l = bf16pk(v0 - h0, v1 - h1);
}
__device__ __forceinline__ void lds2u(uint32_t a, uint32_t& x, uint32_t& y) {
    asm volatile("ld.shared.v2.b32 {%0,%1}, [%2];" : "=r"(x), "=r"(y) : "r"(a));
}
__device__ __forceinline__ uint32_t smem_u32(const void* p) {
    uint32_t a;
    asm("{ .reg .u64 t; cvta.to.shared.u64 t, %1; cvt.u32.u64 %0, t; }" : "=r"(a) : "l"(p));
    return a;
}
__device__ __forceinline__ float qsum(float v) {
    v += __shfl_xor_sync(0xffffffffu, v, 1);
    v += __shfl_xor_sync(0xffffffffu, v, 2);
    return v;
}

// mma matvec: ah/al = KT*4 packed A regs, acc = NT*4 floats (zeroed)
template<int KT, int NT>
__device__ __forceinline__ void mvmma(const uint32_t* ah, const uint32_t* al,
                                      uint32_t sfrag, float* acc, int lane) {
#pragma unroll
    for (int kt = 0; kt < KT; ++kt) {
#pragma unroll
        for (int nt = 0; nt < NT; ++nt) {
            uint32_t off = sfrag + (uint32_t)(((kt * NT + nt) * 64 + lane * 2) * 4);
            uint32_t bh0, bh1, bl0, bl1;
            lds2u(off, bh0, bh1);
            lds2u(off + FRAG_HALF * 4, bl0, bl1);
            float* d = acc + nt * 4;
            mma16(d, ah + kt * 4, bh0, bh1);
            mma16(d, al + kt * 4, bh0, bh1);
            mma16(d, ah + kt * 4, bl0, bl1);
        }
    }
}

// build A fragments (KT k16-tiles) from D-layout values v[NT*4] (NT = 2*KT).
// D cols {2c,2c+1} of n8-tiles 2t,2t+1 are exactly k {2c,2c+1,2c+8,2c+9} of
// k16-tile t -> zero shuffles.
template<int KT>
__device__ __forceinline__ void build_A(const float* v, uint32_t* ah, uint32_t* al) {
#pragma unroll
    for (int t = 0; t < KT; ++t) {
        split2(v[8*t+0], v[8*t+1], ah[4*t+0], al[4*t+0]);   // row lo, k 2c,2c+1
        split2(v[8*t+2], v[8*t+3], ah[4*t+1], al[4*t+1]);   // row hi
        split2(v[8*t+4], v[8*t+5], ah[4*t+2], al[4*t+2]);   // row lo, k+8
        split2(v[8*t+6], v[8*t+7], ah[4*t+3], al[4*t+3]);   // row hi, k+8
    }
}

// load one input (32 wide) for rows rlo/rhi, logmap-scale, build A frags (KT=2)
__device__ __forceinline__ void load_branch_A(const float* __restrict__ gx,
                                              int rlo, int rhi, int c,
                                              uint32_t* ah, uint32_t* al) {
    const float* plo = gx + (size_t)rlo * 32;
    const float* phi = gx + (size_t)rhi * 32;
    float xl[8], xh[8];
#pragma unroll
    for (int t = 0; t < 2; ++t) {
        float2 u = *(const float2*)(plo + 16*t + 2*c);     xl[4*t+0]=u.x; xl[4*t+1]=u.y;
        float2 v = *(const float2*)(plo + 16*t + 2*c + 8); xl[4*t+2]=v.x; xl[4*t+3]=v.y;
        float2 w = *(const float2*)(phi + 16*t + 2*c);     xh[4*t+0]=w.x; xh[4*t+1]=w.y;
        float2 z = *(const float2*)(phi + 16*t + 2*c + 8); xh[4*t+2]=z.x; xh[4*t+3]=z.y;
    }
    float ssl = 0.f, ssh = 0.f;
#pragma unroll
    for (int i = 0; i < 8; ++i) { ssl += xl[i]*xl[i]; ssh += xh[i]*xh[i]; }
    float slo = log_scale(qsum(ssl));
    float shi = log_scale(qsum(ssh));
#pragma unroll
    for (int i = 0; i < 8; ++i) { xl[i] *= slo; xh[i] *= shi; }
#pragma unroll
    for (int t = 0; t < 2; ++t) {
        split2(xl[4*t+0], xl[4*t+1], ah[4*t+0], al[4*t+0]);
        split2(xh[4*t+0], xh[4*t+1], ah[4*t+1], al[4*t+1]);
        split2(xl[4*t+2], xl[4*t+3], ah[4*t+2], al[4*t+2]);
        split2(xh[4*t+2], xh[4*t+3], ah[4*t+3], al[4*t+3]);
    }
}

// ---------------------------------------------------------------------------
// probe kernel: 16 one-hot-k probes; B slots carry s+1 (exact in bf16 <=256)
// ---------------------------------------------------------------------------
__global__ void probe_kernel() {
    __shared__ float sd[128];
    int lane = threadIdx.x;
    int c = lane & 3;
    // canonical init (standard m16n8k16 B layout) as fallback
#pragma unroll
    for (int reg = 0; reg < 2; ++reg)
#pragma unroll
        for (int half = 0; half < 2; ++half) {
            int s = lane * 4 + reg * 2 + half;
            g_ktab[s] = (lane & 3) * 2 + reg * 8 + half;
            g_ntab[s] = lane >> 2;
        }
    uint32_t b0 = bf16pk((float)(lane*4+1), (float)(lane*4+2));
    uint32_t b1 = bf16pk((float)(lane*4+3), (float)(lane*4+4));
#pragma unroll 1
    for (int k0 = 0; k0 < 16; ++k0) {
        uint32_t a[4];
        a[0] = a[1] = bf16pk(2*c == k0 ? 1.f : 0.f, 2*c+1 == k0 ? 1.f : 0.f);
        a[2] = a[3] = bf16pk(2*c+8 == k0 ? 1.f : 0.f, 2*c+9 == k0 ? 1.f : 0.f);
        float d[4] = {0.f, 0.f, 0.f, 0.f};
        mma16(d, a, b0, b1);
        sd[lane*4+0] = d[0]; sd[lane*4+1] = d[1];
        sd[lane*4+2] = d[2]; sd[lane*4+3] = d[3];
        __syncwarp();
        if (lane < 8) {
            int n = lane;
            float val = sd[(n >> 1) * 4 + (n & 1)];     // D row 0, col n
            int s = (int)(val + 0.5f) - 1;
            if (s >= 0 && s < 128) { g_ktab[s] = k0; g_ntab[s] = n; }
        }
        __syncwarp();
    }
}

// ---------------------------------------------------------------------------
// prep kernel: pack matrices into hi/lo bf16 fragments (one u32 per thread)
// ---------------------------------------------------------------------------
__global__ void prep_frags(const float* __restrict__ Wc1, const float* __restrict__ Wc2,
                           const float* __restrict__ W0,  const float* __restrict__ W1)
{
    int idx = blockIdx.x * blockDim.x + threadIdx.x;
    if (idx >= FRAG_HALF) return;
    const float* W; int OUT; int base;
    if (idx < 1024)      { W = Wc1; OUT = 64; base = idx; }
    else if (idx < 2048) { W = Wc2; OUT = 64; base = idx - 1024; }
    else if (idx < 4096) { W = W0;  OUT = 64; base = idx - 2048; }
    else                 { W = W1;  OUT = 32; base = idx - 4096; }
    int NT = OUT / 8;
    int f  = base >> 6;
    int p  = base & 63;              // lane*2 + reg
    int lane = p >> 1, reg = p & 1;
    int kt = f / NT, nt = f % NT;
    int s0 = lane * 4 + reg * 2;
    int k0 = kt * 16 + g_ktab[s0],     n0 = nt * 8 + g_ntab[s0];
    int k1 = kt * 16 + g_ktab[s0 + 1], n1 = nt * 8 + g_ntab[s0 + 1];
    float w0 = W[k0 * OUT + n0];
    float w1 = W[k1 * OUT + n1];
    uint32_t h = bf16pk(w0, w1);
    float h0 = __uint_as_float(h << 16);
    float h1 = __uint_as_float(h & 0xffff0000u);
    g_frag[idx] = h;
    g_frag[FRAG_HALF + idx] = bf16pk(w0 - h0, w1 - h1);
}

// ---------------------------------------------------------------------------
// main kernel: 8 warps x 4 iters x 16 rows = 512 rows per CTA
// ---------------------------------------------------------------------------
#define THREADS 256

__global__ void __launch_bounds__(THREADS, 2)
poincare_mma_kernel(const float* __restrict__ gx1,
                    const float* __restrict__ gx2,
                    const float* __restrict__ gbc,
                    const float* __restrict__ gb0,
                    const float* __restrict__ gb1,
                    float* __restrict__ gout,
                    int N)
{
    extern __shared__ __align__(16) float smf[];
    uint32_t* smu = reinterpret_cast<uint32_t*>(smf);
    {
        uint4* s = reinterpret_cast<uint4*>(smu);
        const uint4* g = reinterpret_cast<const uint4*>(g_frag);
        for (int i = threadIdx.x; i < FRAG_TOTAL / 4; i += THREADS) s[i] = g[i];
        if (threadIdx.x < 64)       smf[FRAG_TOTAL + threadIdx.x] = gbc[threadIdx.x];
        else if (threadIdx.x < 128) smf[FRAG_TOTAL + threadIdx.x] = gb0[threadIdx.x - 64];
        else if (threadIdx.x < 160) smf[FRAG_TOTAL + threadIdx.x] = gb1[threadIdx.x - 128];
    }
    __syncthreads();
    const uint32_t sfrag = smem_u32(smu);
    const float* sbc = smf + FRAG_TOTAL;
    const float* sb0 = sbc + 64;
    const float* sb1 = sb0 + 64;

    const int wid = threadIdx.x >> 5;
    const int lane = threadIdx.x & 31;
    const int c = lane & 3;

    float bc2 = 0.f, b0sq = 0.f, b1sq = 0.f;
    for (int i = 0; i < 64; ++i) { bc2 += sbc[i] * sbc[i]; b0sq += sb0[i] * sb0[i]; }
    for (int i = 0; i < 32; ++i) b1sq += sb1[i] * sb1[i];

#pragma unroll 1
    for (int it = 0; it < 4; ++it) {
        const int rbase = (blockIdx.x * 32 + it * 8 + wid) * 16;
        int rlo = rbase + (lane >> 2);
        int rhi = rlo + 8;
        rlo = rlo < N ? rlo : N - 1;
        rhi = rhi < N ? rhi : N - 1;

        float raw1[32], raw2[32];
        {
            uint32_t ah[8], al[8];
            load_branch_A(gx1, rlo, rhi, c, ah, al);
#pragma unroll
            for (int j = 0; j < 32; ++j) raw1[j] = 0.f;
            mvmma<2, 8>(ah, al, sfrag + FOFF_WC1 * 4, raw1, lane);

            load_branch_A(gx2, rlo, rhi, c, ah, al);
#pragma unroll
            for (int j = 0; j < 32; ++j) raw2[j] = 0.f;
            mvmma<2, 8>(ah, al, sfrag + FOFF_WC2 * 4, raw2, lane);
        }

        // ---- fused concat chain; v overwrites raw1 ----
        {
            float aa_l = 0, bb_l = 0, ab_l = 0, ac_l = 0, bd_l = 0;
            float aa_h = 0, bb_h = 0, ab_h = 0, ac_h = 0, bd_h = 0;
#pragma unroll
            for (int nt = 0; nt < 8; ++nt) {
                float2 bcv = *(const float2*)(sbc + nt * 8 + 2 * c);
                float p0 = raw1[nt*4], p1 = raw1[nt*4+1], p2 = raw1[nt*4+2], p3 = raw1[nt*4+3];
                float q0 = raw2[nt*4], q1 = raw2[nt*4+1], q2 = raw2[nt*4+2], q3 = raw2[nt*4+3];
                aa_l += p0*p0 + p1*p1;  aa_h += p2*p2 + p3*p3;
                bb_l += q0*q0 + q1*q1;  bb_h += q2*q2 + q3*q3;
                ab_l += p0*q0 + p1*q1;  ab_h += p2*q2 + p3*q3;
                ac_l += p0*bcv.x + p1*bcv.y;  ac_h += p2*bcv.x + p3*bcv.y;
                bd_l += q0*bcv.x + q1*bcv.y;  bd_h += q2*bcv.x + q3*bcv.y;
            }
            aa_l = qsum(aa_l); bb_l = qsum(bb_l); ab_l = qsum(ab_l);
            ac_l = qsum(ac_l); bd_l = qsum(bd_l);
            aa_h = qsum(aa_h); bb_h = qsum(bb_h); ab_h = qsum(ab_h);
            ac_h = qsum(ac_h); bd_h = qsum(bd_h);
            float fa_l, fb_l, fc_l, fa_h, fb_h, fc_h;
            concat_coefs(aa_l, bb_l, ab_l, ac_l, bd_l, bc2, fa_l, fb_l, fc_l);
            concat_coefs(aa_h, bb_h, ab_h, ac_h, bd_h, bc2, fa_h, fb_h, fc_h);
#pragma unroll
            for (int nt = 0; nt < 8; ++nt) {
                float2 bcv = *(const float2*)(sbc + nt * 8 + 2 * c);
                raw1[nt*4+0] = fa_l * raw1[nt*4+0] + fb_l * raw2[nt*4+0] + fc_l * bcv.x;
                raw1[nt*4+1] = fa_l * raw1[nt*4+1] + fb_l * raw2[nt*4+1] + fc_l * bcv.y;
                raw1[nt*4+2] = fa_h * raw1[nt*4+2] + fb_h * raw2[nt*4+2] + fc_h * bcv.x;
                raw1[nt*4+3] = fa_h * raw1[nt*4+3] + fb_h * raw2[nt*4+3] + fc_h * bcv.y;
            }
        }

        // ---- layer 0: build A (no shuffles) -> mma ----
        float raw3[32];
        {
            uint32_t ah[16], al[16];
            build_A<4>(raw1, ah, al);
#pragma unroll
            for (int j = 0; j < 32; ++j) raw3[j] = 0.f;
            mvmma<4, 8>(ah, al, sfrag + FOFF_W0 * 4, raw3, lane);
        }

        // layer-0 chain; v2 overwrites raw3
        {
            float ss_l = 0, dd_l = 0, ss_h = 0, dd_h = 0;
#pragma unroll
            for (int nt = 0; nt < 8; ++nt) {
                float2 bv = *(const float2*)(sb0 + nt * 8 + 2 * c);
                float p0 = raw3[nt*4], p1 = raw3[nt*4+1], p2 = raw3[nt*4+2], p3 = raw3[nt*4+3];
                ss_l += p0*p0 + p1*p1;  ss_h += p2*p2 + p3*p3;
                dd_l += p0*bv.x + p1*bv.y;  dd_h += p2*bv.x + p3*bv.y;
            }
            ss_l = qsum(ss_l); dd_l = qsum(dd_l);
            ss_h = qsum(ss_h); dd_h = qsum(dd_h);
            float fg_l, fd_l, fg_h, fd_h;
            layer_coefs(ss_l, dd_l, b0sq, fg_l, fd_l);
            layer_coefs(ss_h, dd_h, b0sq, fg_h, fd_h);
#pragma unroll
            for (int nt = 0; nt < 8; ++nt) {
                float2 bv = *(const float2*)(sb0 + nt * 8 + 2 * c);
                raw3[nt*4+0] = fg_l * raw3[nt*4+0] + fd_l * bv.x;
                raw3[nt*4+1] = fg_l * raw3[nt*4+1] + fd_l * bv.y;
                raw3[nt*4+2] = fg_h * raw3[nt*4+2] + fd_h * bv.x;
                raw3[nt*4+3] = fg_h * raw3[nt*4+3] + fd_h * bv.y;
            }
        }

        // ---- layer 1 ----
        float raw4[16];
        {
            uint32_t ah[16], al[16];
            build_A<4>(raw3, ah, al);
#pragma unroll
            for (int j = 0; j < 16; ++j) raw4[j] = 0.f;
            mvmma<4, 4>(ah, al, sfrag + FOFF_W1 * 4, raw4, lane);
        }

        // output chain + store
        {
            float ss_l = 0, dd_l = 0, ss_h = 0, dd_h = 0;
#pragma unroll
            for (int nt = 0; nt < 4; ++nt) {
                float2 bv = *(const float2*)(sb1 + nt * 8 + 2 * c);
                float p0 = raw4[nt*4], p1 = raw4[nt*4+1], p2 = raw4[nt*4+2], p3 = raw4[nt*4+3];
                ss_l += p0*p0 + p1*p1;  ss_h += p2*p2 + p3*p3;
                dd_l += p0*bv.x + p1*bv.y;  dd_h += p2*bv.x + p3*bv.y;
            }
            ss_l = qsum(ss_l); dd_l = qsum(dd_l);
            ss_h = qsum(ss_h); dd_h = qsum(dd_h);
            float pa_l, pb_l, pa_h, pb_h;
            out_coefs(ss_l, dd_l, b1sq, pa_l, pb_l);
            out_coefs(ss_h, dd_h, b1sq, pa_h, pb_h);
            float* olo = gout + (size_t)rlo * 32;
            float* ohi = gout + (size_t)rhi * 32;
#pragma unroll
            for (int nt = 0; nt < 4; ++nt) {
                float2 bv = *(const float2*)(sb1 + nt * 8 + 2 * c);
                float2 vlo = make_float2(pa_l * raw4[nt*4+0] + pb_l * bv.x,
                                         pa_l * raw4[nt*4+1] + pb_l * bv.y);
                float2 vhi = make_float2(pa_h * raw4[nt*4+2] + pb_h * bv.x,
                                         pa_h * raw4[nt*4+3] + pb_h * bv.y);
                *reinterpret_cast<float2*>(olo + nt * 8 + 2 * c) = vlo;
                *reinterpret_cast<float2*>(ohi + nt * 8 + 2 * c) = vhi;
            }
        }
    }
}

// ---------------------------------------------------------------------------
// launch: probe -> prep -> main
// ---------------------------------------------------------------------------
extern "C" void kernel_launch(void* const* d_in, const int* in_sizes, int n_in,
                              void* d_out, int out_size)
{
    const float* x1  = (const float*)d_in[0];
    const float* x2  = (const float*)d_in[1];
    const float* Wc1 = (const float*)d_in[2];
    const float* Wc2 = (const float*)d_in[3];
    const float* bc  = (const float*)d_in[4];
    const float* W0  = (const float*)d_in[5];
    const float* b0  = (const float*)d_in[6];
    const float* W1  = (const float*)d_in[7];
    const float* b1  = (const float*)d_in[8];
    float* out = (float*)d_out;

    probe_kernel<<<1, 32>>>();
    prep_frags<<<20, 256>>>(Wc1, Wc2, W0, W1);

    const int smem_bytes = FRAG_TOTAL * 4 + 160 * 4;
    cudaFuncSetAttribute(poincare_mma_kernel,
                         cudaFuncAttributeMaxDynamicSharedMemorySize, smem_bytes);

    const int N = in_sizes[0] / 32;
    const int rows_per_cta = 512;
    const int blocks = (N + rows_per_cta - 1) / rows_per_cta;
    poincare_mma_kernel<<<blocks, THREADS, smem_bytes>>>(x1, x2, bc, b0, b1, out, N);
}